// round 13
// baseline (speedup 1.0000x reference)
#include <cuda_runtime.h>
#include <math.h>

// ---------------- Problem constants ----------------
#define BB   128
#define LL   128
#define JJ   64
#define EE   128
#define SS   129
#define HH   2
#define HD   64
#define CATN 1000
#define AMTN 100
#define ROWS (BB*SS)   // 16512 = 258 * 64

// ---------------- fused mma-attention geometry (v3: pre-rounded tf32) ------
#define MCH    48
#define NCHUNK 3
#define SPN    136
#define SSP    140
#define KTP    136
#define VP     72
#define QP     68
#define SS_FLOATS   (MCH*SSP)
#define SKT_FLOATS  (64*KTP)
#define SUN_FLOATS  (SPN*VP)
#define ATTN_SMEM_BYTES ((SS_FLOATS + SKT_FLOATS + SUN_FLOATS) * 4)  // 100864

// ---------------- embed v2 geometry ----------------
#define ECH 32                               // floats of E per chunk
#define EMB_CAT_FLOATS (CATN*ECH)            // 32000
#define EMB_AMT_FLOATS (AMTN*ECH)            // 3200
#define EMB_SMEM_BYTES ((EMB_CAT_FLOATS + EMB_AMT_FLOATS)*4 + 8*JJ*2*4)  // 144896

// ---------------- Device scratch ----------------
__device__ float g_x  [ROWS*EE];
__device__ float g_q  [ROWS*EE];
__device__ float g_k  [ROWS*EE];
__device__ float g_v  [ROWS*EE];
__device__ float g_o  [ROWS*EE];
__device__ float g_tmp[ROWS*EE];
__device__ float g_f1 [ROWS*EE];
__device__ float g_f2 [ROWS*EE];
__device__ float g_h  [BB*EE];
__device__ float g_x1 [BB*CATN];

// ---------------- TF32 / cp.async helpers ----------------
__device__ __forceinline__ unsigned f2tf(float x) {
    unsigned u;
    asm("cvt.rna.tf32.f32 %0, %1;" : "=r"(u) : "f"(x));
    return u;
}
__device__ __forceinline__ float rnd_tf(float x) {
    return __uint_as_float(f2tf(x));
}
__device__ __forceinline__ void mma_tf32(float* d, const unsigned* a, const unsigned* b) {
    asm volatile(
        "mma.sync.aligned.m16n8k8.row.col.f32.tf32.tf32.f32 "
        "{%0,%1,%2,%3}, {%4,%5,%6,%7}, {%8,%9}, {%0,%1,%2,%3};\n"
        : "+f"(d[0]), "+f"(d[1]), "+f"(d[2]), "+f"(d[3])
        : "r"(a[0]), "r"(a[1]), "r"(a[2]), "r"(a[3]), "r"(b[0]), "r"(b[1]));
}
__device__ __forceinline__ void cp_async16(void* smem, const void* gmem) {
    unsigned s = (unsigned)__cvta_generic_to_shared(smem);
    asm volatile("cp.async.ca.shared.global [%0], [%1], 16;\n" :: "r"(s), "l"(gmem));
}

// ---------------- Single-pass TF32 GEMM, 64x128 tile, BK=16, cp.async ------
__global__ __launch_bounds__(256)
void gemm_tf32(const float* __restrict__ A,
               const float* __restrict__ Wa, const float* __restrict__ Wb,
               const float* __restrict__ Wc,
               const float* __restrict__ ba, const float* __restrict__ bb,
               const float* __restrict__ bc,
               float* __restrict__ Ca, float* __restrict__ Cb, float* __restrict__ Cc,
               int N, int K, int relu)
{
    const float* W    = (blockIdx.z == 0) ? Wa : (blockIdx.z == 1) ? Wb : Wc;
    const float* bias = (blockIdx.z == 0) ? ba : (blockIdx.z == 1) ? bb : bc;
    float*       C    = (blockIdx.z == 0) ? Ca : (blockIdx.z == 1) ? Cb : Cc;

    __shared__ __align__(16) float As[2][64][20];
    __shared__ __align__(16) float Bs[2][16][136];

    const int bm = blockIdx.y * 64;
    const int tid = threadIdx.x, warp = tid >> 5, lane = tid & 31;
    const int wm = warp & 1, wn = warp >> 1;
    const int g = lane >> 2, t = lane & 3;

    const int ra = tid >> 2,  ca = (tid & 3) * 4;
    const int rb = tid >> 5,  cb = (tid & 31) * 4;

    float acc[2][4][4] = {};

    const int niter = K >> 4;
    cp_async16(&As[0][ra][ca],   A + (size_t)(bm + ra) * K + ca);
    cp_async16(&Bs[0][rb][cb],   W + (size_t)rb * N + cb);
    cp_async16(&Bs[0][rb+8][cb], W + (size_t)(rb + 8) * N + cb);
    asm volatile("cp.async.commit_group;\n");

    for (int it = 0; it < niter; it++) {
        const int cur = it & 1;
        if (it + 1 < niter) {
            const int nxt = cur ^ 1, k0 = (it + 1) << 4;
            cp_async16(&As[nxt][ra][ca],   A + (size_t)(bm + ra) * K + k0 + ca);
            cp_async16(&Bs[nxt][rb][cb],   W + (size_t)(k0 + rb) * N + cb);
            cp_async16(&Bs[nxt][rb+8][cb], W + (size_t)(k0 + rb + 8) * N + cb);
            asm volatile("cp.async.commit_group;\n");
            asm volatile("cp.async.wait_group 1;\n");
        } else {
            asm volatile("cp.async.wait_group 0;\n");
        }
        __syncthreads();

        #pragma unroll
        for (int kk = 0; kk < 16; kk += 8) {
            unsigned a[2][4], bfr[4][2];
            #pragma unroll
            for (int i = 0; i < 2; i++) {
                int row = wm*32 + i*16 + g;
                a[i][0] = f2tf(As[cur][row    ][kk + t    ]);
                a[i][1] = f2tf(As[cur][row + 8][kk + t    ]);
                a[i][2] = f2tf(As[cur][row    ][kk + t + 4]);
                a[i][3] = f2tf(As[cur][row + 8][kk + t + 4]);
            }
            #pragma unroll
            for (int j = 0; j < 4; j++) {
                int col = wn*32 + j*8 + g;
                bfr[j][0] = f2tf(Bs[cur][kk + t    ][col]);
                bfr[j][1] = f2tf(Bs[cur][kk + t + 4][col]);
            }
            #pragma unroll
            for (int i = 0; i < 2; i++)
                #pragma unroll
                for (int j = 0; j < 4; j++)
                    mma_tf32(acc[i][j], a[i], bfr[j]);
        }
        __syncthreads();
    }

    #pragma unroll
    for (int i = 0; i < 2; i++) {
        #pragma unroll
        for (int half = 0; half < 2; half++) {
            int r = bm + wm*32 + i*16 + g + half*8;
            #pragma unroll
            for (int j = 0; j < 4; j++) {
                int n0 = wn*32 + j*8 + 2*t;
                float d0 = acc[i][j][half*2]     + bias[n0];
                float d1 = acc[i][j][half*2 + 1] + bias[n0 + 1];
                if (relu) { d0 = fmaxf(d0, 0.f); d1 = fmaxf(d1, 0.f); }
                C[(size_t)r*N + n0]     = d0;
                C[(size_t)r*N + n0 + 1] = d1;
            }
        }
    }
}

// ---------------- Head GEMM (small M, fp32) --------------------------------
__global__ __launch_bounds__(128)
void head_gemm(const float* __restrict__ A, const float* __restrict__ W,
               const float* __restrict__ bias, float* __restrict__ C,
               int M, int N, int K, int relu)
{
    __shared__ __align__(16) float As[8][128];
    const int bn = blockIdx.x * 128, bm = blockIdx.y * 8;
    const int tid = threadIdx.x;
    const int n = bn + tid;
    float acc[8] = {};
    for (int k0 = 0; k0 < K; k0 += 128) {
        int kc = min(128, K - k0);
        #pragma unroll
        for (int i = 0; i < 8; i++)
            As[i][tid] = (tid < kc) ? A[(size_t)(bm + i)*K + k0 + tid] : 0.f;
        __syncthreads();
        if (n < N) {
            for (int k = 0; k < kc; k += 4) {
                float w0 = W[(size_t)(k0 + k    )*N + n];
                float w1 = W[(size_t)(k0 + k + 1)*N + n];
                float w2 = W[(size_t)(k0 + k + 2)*N + n];
                float w3 = W[(size_t)(k0 + k + 3)*N + n];
                #pragma unroll
                for (int i = 0; i < 8; i++) {
                    float4 a = *reinterpret_cast<const float4*>(&As[i][k]);
                    acc[i] += a.x*w0 + a.y*w1 + a.z*w2 + a.w*w3;
                }
            }
        }
        __syncthreads();
    }
    if (n < N) {
        #pragma unroll
        for (int i = 0; i < 8; i++) {
            float v = acc[i] + bias[n];
            if (relu) v = fmaxf(v, 0.f);
            C[(size_t)(bm + i)*N + n] = v;
        }
    }
}

// ---------------- Embedding v2: tables staged in shared memory -------------
// grid = (64 bag-groups, 4 e-chunks); block = 256 (8 warps).
// Each block stages the 32-float e-chunk of cat_table (128KB) + amt_table
// (12.8KB) into smem; 8 warps sweep 32 bags each with conflict-free LDS.
__global__ __launch_bounds__(256)
void embed_kernel2(const int* __restrict__ cat_arr,
                   const int* __restrict__ amt_arr,
                   const int* __restrict__ dt_arr,
                   const float* __restrict__ cat_tab,
                   const float* __restrict__ amt_tab,
                   const float* __restrict__ dt_tab,
                   float* __restrict__ x)
{
    extern __shared__ float sm[];
    float* cat_s = sm;                              // [CATN*ECH]
    float* amt_s = sm + EMB_CAT_FLOATS;             // [AMTN*ECH]
    int*   sc    = (int*)(amt_s + EMB_AMT_FLOATS);  // [8][64]
    int*   sa    = sc + 8*JJ;                       // [8][64]

    const int tid = threadIdx.x, w = tid >> 5, lane = tid & 31;
    const int e0 = blockIdx.y * ECH;

    // stage cat table e-chunk (coalesced 128B rows)
    for (int i = tid; i < EMB_CAT_FLOATS; i += 256) {
        int row = i >> 5, c = i & 31;
        cat_s[i] = cat_tab[(size_t)row*EE + e0 + c];
    }
    // stage amt table e-chunk
    for (int i = tid; i < EMB_AMT_FLOATS; i += 256) {
        int row = i >> 5, c = i & 31;
        amt_s[i] = amt_tab[(size_t)row*EE + e0 + c];
    }
    __syncthreads();

    const int bag0 = blockIdx.x * 256 + w * 32;
    for (int it = 0; it < 32; it++) {
        int bag = bag0 + it;
        // load this bag's 64 indices into per-warp smem
        sc[w*JJ + lane]      = cat_arr[(size_t)bag*JJ + lane];
        sc[w*JJ + lane + 32] = cat_arr[(size_t)bag*JJ + lane + 32];
        sa[w*JJ + lane]      = amt_arr[(size_t)bag*JJ + lane];
        sa[w*JJ + lane + 32] = amt_arr[(size_t)bag*JJ + lane + 32];
        __syncwarp();
        float acc = 0.f;
        #pragma unroll 4
        for (int j = 0; j < JJ; j++) {
            int c = sc[w*JJ + j];
            if (c != CATN)
                acc += cat_s[c*ECH + lane] + amt_s[sa[w*JJ + j]*ECH + lane];
        }
        acc += dt_tab[(size_t)dt_arr[bag]*EE + e0 + lane];
        int b = bag >> 7, l = bag & 127;
        x[((size_t)b*SS + l + 1)*EE + e0 + lane] = acc;
        __syncwarp();
    }
}

__global__ void id_kernel(const int* __restrict__ id_arr,
                          const float* __restrict__ id_tab)
{
    int b = blockIdx.x, e = threadIdx.x;
    g_x[(size_t)b*SS*EE + e] = id_tab[(size_t)id_arr[b]*EE + e];
}

// ---------------- Fused tensor-core attention v3 (single-pass tf32) --------
__global__ __launch_bounds__(256)
void attn_mma(const float* __restrict__ q, const float* __restrict__ k,
              const float* __restrict__ v, float* __restrict__ o)
{
    extern __shared__ float smem[];
    float* sS  = smem;
    float* sKT = smem + SS_FLOATS;
    float* sU  = sKT + SKT_FLOATS;

    const int blk = blockIdx.x;
    const int chunk = blk % NCHUNK;
    const int bh = blk / NCHUNK;
    const int b = bh >> 1, h = bh & 1;
    const int row0 = chunk * MCH;

    const int tid = threadIdx.x, wid = tid >> 5, lane = tid & 31;
    const int g = lane >> 2, t = lane & 3;

    {
        float* sQ = sU;
        for (int idx = tid; idx < MCH*16; idx += 256) {
            int r = idx >> 4, dc = (idx & 15) * 4;
            int i = row0 + r;
            float4 tq = make_float4(0.f, 0.f, 0.f, 0.f);
            if (i < SS)
                tq = *reinterpret_cast<const float4*>(&q[((size_t)b*SS + i)*EE + h*HD + dc]);
            sQ[r*QP + dc    ] = rnd_tf(tq.x);
            sQ[r*QP + dc + 1] = rnd_tf(tq.y);
            sQ[r*QP + dc + 2] = rnd_tf(tq.z);
            sQ[r*QP + dc + 3] = rnd_tf(tq.w);
        }
    }
    for (int idx = tid; idx < SS*16; idx += 256) {
        int j = idx >> 4, dc = (idx & 15) * 4;
        float4 tk = *reinterpret_cast<const float4*>(&k[((size_t)b*SS + j)*EE + h*HD + dc]);
        sKT[(dc    )*KTP + j] = rnd_tf(tk.x);
        sKT[(dc + 1)*KTP + j] = rnd_tf(tk.y);
        sKT[(dc + 2)*KTP + j] = rnd_tf(tk.z);
        sKT[(dc + 3)*KTP + j] = rnd_tf(tk.w);
    }
    for (int idx = tid; idx < 64*(SPN - SS); idx += 256) {
        int d = idx / (SPN - SS), j = SS + idx % (SPN - SS);
        sKT[d*KTP + j] = 0.f;
    }
    __syncthreads();

    {
        const float* sQ = sU;
        for (int tile = wid; tile < 3*17; tile += 8) {
            int tm = tile / 17, tn = tile % 17;
            int r0 = tm*16 + g, col = tn*8 + g;
            float acc[4] = {0.f, 0.f, 0.f, 0.f};
            #pragma unroll
            for (int ks = 0; ks < 8; ks++) {
                int kk = ks * 8;
                unsigned a[4], bfr[2];
                a[0] = __float_as_uint(sQ[(r0    )*QP + kk + t    ]);
                a[1] = __float_as_uint(sQ[(r0 + 8)*QP + kk + t    ]);
                a[2] = __float_as_uint(sQ[(r0    )*QP + kk + t + 4]);
                a[3] = __float_as_uint(sQ[(r0 + 8)*QP + kk + t + 4]);
                bfr[0] = __float_as_uint(sKT[(kk + t    )*KTP + col]);
                bfr[1] = __float_as_uint(sKT[(kk + t + 4)*KTP + col]);
                mma_tf32(acc, a, bfr);
            }
            int c0 = tn*8 + 2*t;
            sS[(r0    )*SSP + c0    ] = acc[0] * 0.125f;
            sS[(r0    )*SSP + c0 + 1] = acc[1] * 0.125f;
            sS[(r0 + 8)*SSP + c0    ] = acc[2] * 0.125f;
            sS[(r0 + 8)*SSP + c0 + 1] = acc[3] * 0.125f;
        }
    }
    __syncthreads();

    for (int r = wid; r < MCH; r += 8) {
        int i = row0 + r;
        if (i < SS) {
            float pr[5];
            float mx = -1e30f;
            #pragma unroll
            for (int m = 0; m < 5; m++) {
                int j = lane + m*32;
                float s = (j < SS) ? sS[r*SSP + j] : -1e30f;
                pr[m] = s;
                mx = fmaxf(mx, s);
            }
            #pragma unroll
            for (int off = 16; off > 0; off >>= 1)
                mx = fmaxf(mx, __shfl_xor_sync(0xffffffffu, mx, off));
            float sum = 0.f;
            #pragma unroll
            for (int m = 0; m < 5; m++) {
                int j = lane + m*32;
                float e = (j < SS) ? __expf(pr[m] - mx) : 0.f;
                pr[m] = e; sum += e;
            }
            #pragma unroll
            for (int off = 16; off > 0; off >>= 1)
                sum += __shfl_xor_sync(0xffffffffu, sum, off);
            float inv = 1.f / sum;
            #pragma unroll
            for (int m = 0; m < 5; m++) {
                int j = lane + m*32;
                if (j < SPN)
                    sS[r*SSP + j] = (j < SS) ? rnd_tf(pr[m] * inv) : 0.f;
            }
        } else {
            #pragma unroll
            for (int m = 0; m < 5; m++) {
                int j = lane + m*32;
                if (j < SPN) sS[r*SSP + j] = 0.f;
            }
        }
    }
    {
        float* sV = sU;
        for (int idx = tid; idx < SPN*16; idx += 256) {
            int j = idx >> 4, dc = (idx & 15) * 4;
            float4 tv = make_float4(0.f, 0.f, 0.f, 0.f);
            if (j < SS)
                tv = *reinterpret_cast<const float4*>(&v[((size_t)b*SS + j)*EE + h*HD + dc]);
            sV[j*VP + dc    ] = rnd_tf(tv.x);
            sV[j*VP + dc + 1] = rnd_tf(tv.y);
            sV[j*VP + dc + 2] = rnd_tf(tv.z);
            sV[j*VP + dc + 3] = rnd_tf(tv.w);
        }
    }
    __syncthreads();

    {
        const float* sV = sU;
        for (int tile = wid; tile < 3*8; tile += 8) {
            int tm = tile >> 3, tn = tile & 7;
            int r0 = tm*16 + g, col = tn*8 + g;
            float acc[4] = {0.f, 0.f, 0.f, 0.f};
            #pragma unroll
            for (int ks = 0; ks < 17; ks++) {
                int kk = ks * 8;
                unsigned a[4], bfr[2];
                a[0] = __float_as_uint(sS[(r0    )*SSP + kk + t    ]);
                a[1] = __float_as_uint(sS[(r0 + 8)*SSP + kk + t    ]);
                a[2] = __float_as_uint(sS[(r0    )*SSP + kk + t + 4]);
                a[3] = __float_as_uint(sS[(r0 + 8)*SSP + kk + t + 4]);
                bfr[0] = __float_as_uint(sV[(kk + t    )*VP + col]);
                bfr[1] = __float_as_uint(sV[(kk + t + 4)*VP + col]);
                mma_tf32(acc, a, bfr);
            }
            int c0 = tn*8 + 2*t;
            int i0 = row0 + tm*16 + g;
            if (i0 < SS) {
                float* orow = &o[((size_t)b*SS + i0)*EE + h*HD];
                orow[c0] = acc[0]; orow[c0 + 1] = acc[1];
            }
            if (i0 + 8 < SS) {
                float* orow = &o[((size_t)b*SS + i0 + 8)*EE + h*HD];
                orow[c0] = acc[2]; orow[c0 + 1] = acc[3];
            }
        }
    }
}

// ---------------- LayerNorm(x + add) in place ----------------
__global__ void ln_add(float* __restrict__ x, const float* __restrict__ add,
                       const float* __restrict__ g, const float* __restrict__ bta)
{
    int r = blockIdx.x, e = threadIdx.x;
    __shared__ float red[4];
    float v = x[(size_t)r*EE + e] + add[(size_t)r*EE + e];
    float s = v;
    #pragma unroll
    for (int o = 16; o > 0; o >>= 1) s += __shfl_xor_sync(0xffffffffu, s, o);
    if ((e & 31) == 0) red[e >> 5] = s;
    __syncthreads();
    float mu = (red[0] + red[1] + red[2] + red[3]) * (1.f/128.f);
    __syncthreads();
    float d = v - mu;
    float s2 = d * d;
    #pragma unroll
    for (int o = 16; o > 0; o >>= 1) s2 += __shfl_xor_sync(0xffffffffu, s2, o);
    if ((e & 31) == 0) red[e >> 5] = s2;
    __syncthreads();
    float var = (red[0] + red[1] + red[2] + red[3]) * (1.f/128.f);
    x[(size_t)r*EE + e] = d * rsqrtf(var + 1e-5f) * g[e] + bta[e];
}

// ---------------- Mean pool ----------------
__global__ void pool_kernel(const float* __restrict__ x, float* __restrict__ h)
{
    int b = blockIdx.x, e = threadIdx.x;
    float s = 0.f;
    #pragma unroll 4
    for (int l = 1; l <= LL; l++) s += x[((size_t)b*SS + l)*EE + e];
    h[(size_t)b*EE + e] = s * (1.f/128.f);
}

// ---------------- Launch ----------------
extern "C" void kernel_launch(void* const* d_in, const int* in_sizes, int n_in,
                              void* d_out, int out_size)
{
    (void)in_sizes; (void)n_in; (void)out_size;
    const int*   cat_arr = (const int*)  d_in[0];
    const int*   dt_arr  = (const int*)  d_in[1];
    const int*   amt_arr = (const int*)  d_in[2];
    const int*   id_arr  = (const int*)  d_in[3];
    const float* id_tab  = (const float*)d_in[4];
    const float* cat_tab = (const float*)d_in[5];
    const float* amt_tab = (const float*)d_in[6];
    const float* dt_tab  = (const float*)d_in[7];
    const float* Wq = (const float*)d_in[8],  *bq = (const float*)d_in[9];
    const float* Wk = (const float*)d_in[10], *bk = (const float*)d_in[11];
    const float* Wv = (const float*)d_in[12], *bv = (const float*)d_in[13];
    const float* Wo = (const float*)d_in[14], *bo = (const float*)d_in[15];
    const float* ln1g = (const float*)d_in[16], *ln1b = (const float*)d_in[17];
    const float* W1 = (const float*)d_in[18], *b1 = (const float*)d_in[19];
    const float* W2 = (const float*)d_in[20], *b2 = (const float*)d_in[21];
    const float* ln2g = (const float*)d_in[22], *ln2b = (const float*)d_in[23];
    const float* l1W = (const float*)d_in[24], *l1b = (const float*)d_in[25];
    const float* l2W = (const float*)d_in[26], *l2b = (const float*)d_in[27];
    float* out = (float*)d_out;

    float *x, *q, *k, *v, *o, *tmp, *f1, *f2, *h, *x1;
    cudaGetSymbolAddress((void**)&x,   g_x);
    cudaGetSymbolAddress((void**)&q,   g_q);
    cudaGetSymbolAddress((void**)&k,   g_k);
    cudaGetSymbolAddress((void**)&v,   g_v);
    cudaGetSymbolAddress((void**)&o,   g_o);
    cudaGetSymbolAddress((void**)&tmp, g_tmp);
    cudaGetSymbolAddress((void**)&f1,  g_f1);
    cudaGetSymbolAddress((void**)&f2,  g_f2);
    cudaGetSymbolAddress((void**)&h,   g_h);
    cudaGetSymbolAddress((void**)&x1,  g_x1);

    static int smem_set = 0;
    if (!smem_set) {
        cudaFuncSetAttribute(attn_mma,
                             cudaFuncAttributeMaxDynamicSharedMemorySize,
                             ATTN_SMEM_BYTES);
        cudaFuncSetAttribute(embed_kernel2,
                             cudaFuncAttributeMaxDynamicSharedMemorySize,
                             EMB_SMEM_BYTES);
        smem_set = 1;
    }

    // 1. embeddings (smem-staged tables)
    dim3 gEmb(64, 4);
    embed_kernel2<<<gEmb, 256, EMB_SMEM_BYTES>>>(cat_arr, amt_arr, dt_arr,
                                                 cat_tab, amt_tab, dt_tab, x);
    id_kernel<<<BB, EE>>>(id_arr, id_tab);

    // 2. QKV: one batched launch (z = 0,1,2)
    dim3 gQKV(1, ROWS/64, 3);
    gemm_tf32<<<gQKV, 256>>>(x, Wq, Wk, Wv, bq, bk, bv, q, k, v, EE, EE, 0);

    // 3. fused tensor-core attention (single-pass tf32)
    attn_mma<<<BB*HH*NCHUNK, 256, ATTN_SMEM_BYTES>>>(q, k, v, o);

    // 4. out proj + residual + LN1
    dim3 g1(1, ROWS/64, 1);
    gemm_tf32<<<g1, 256>>>(o, Wo, Wo, Wo, bo, bo, bo, tmp, tmp, tmp, EE, EE, 0);
    ln_add<<<ROWS, EE>>>(x, tmp, ln1g, ln1b);

    // 5. FFN + residual + LN2
    gemm_tf32<<<g1, 256>>>(x,  W1, W1, W1, b1, b1, b1, f1, f1, f1, EE, EE, 1);
    gemm_tf32<<<g1, 256>>>(f1, W2, W2, W2, b2, b2, b2, f2, f2, f2, EE, EE, 0);
    ln_add<<<ROWS, EE>>>(x, f2, ln2g, ln2b);

    // 6. pool + classifier head
    pool_kernel<<<BB, EE>>>(x, h);
    dim3 gH1((CATN + 127)/128, BB/8);
    head_gemm<<<gH1, 128>>>(h,  l1W, l1b, x1,  BB, CATN, EE,   1);
    head_gemm<<<gH1, 128>>>(x1, l2W, l2b, out, BB, CATN, CATN, 0);
}

// round 15
// speedup vs baseline: 2.0510x; 2.0510x over previous
#include <cuda_runtime.h>
#include <math.h>

// ---------------- Problem constants ----------------
#define BB   128
#define LL   128
#define JJ   64
#define EE   128
#define SS   129
#define HH   2
#define HD   64
#define CATN 1000
#define ROWS (BB*SS)   // 16512 = 258 * 64

// ---------------- fused mma-attention geometry (v3: pre-rounded tf32) ------
#define MCH    48
#define NCHUNK 3
#define SPN    136
#define SSP    140
#define KTP    136
#define VP     72
#define QP     68
#define SS_FLOATS   (MCH*SSP)
#define SKT_FLOATS  (64*KTP)
#define SUN_FLOATS  (SPN*VP)
#define ATTN_SMEM_BYTES ((SS_FLOATS + SKT_FLOATS + SUN_FLOATS) * 4)  // 100864

// ---------------- Device scratch ----------------
__device__ float g_x  [ROWS*EE];
__device__ float g_q  [ROWS*EE];
__device__ float g_k  [ROWS*EE];
__device__ float g_v  [ROWS*EE];
__device__ float g_o  [ROWS*EE];
__device__ float g_f1 [ROWS*EE];
__device__ float g_h  [BB*EE];
__device__ float g_x1 [BB*CATN];

// ---------------- TF32 / cp.async helpers ----------------
__device__ __forceinline__ unsigned f2tf(float x) {
    unsigned u;
    asm("cvt.rna.tf32.f32 %0, %1;" : "=r"(u) : "f"(x));
    return u;
}
__device__ __forceinline__ float rnd_tf(float x) {
    return __uint_as_float(f2tf(x));
}
__device__ __forceinline__ void mma_tf32(float* d, const unsigned* a, const unsigned* b) {
    asm volatile(
        "mma.sync.aligned.m16n8k8.row.col.f32.tf32.tf32.f32 "
        "{%0,%1,%2,%3}, {%4,%5,%6,%7}, {%8,%9}, {%0,%1,%2,%3};\n"
        : "+f"(d[0]), "+f"(d[1]), "+f"(d[2]), "+f"(d[3])
        : "r"(a[0]), "r"(a[1]), "r"(a[2]), "r"(a[3]), "r"(b[0]), "r"(b[1]));
}
__device__ __forceinline__ void cp_async16(void* smem, const void* gmem) {
    unsigned s = (unsigned)__cvta_generic_to_shared(smem);
    asm volatile("cp.async.ca.shared.global [%0], [%1], 16;\n" :: "r"(s), "l"(gmem));
}

// ---------------- Single-pass TF32 GEMM, 64x128 tile, BK=16, cp.async ------
// Optional fused epilogue: out = LayerNorm(resid + (A@W + bias)).
// smem union: C-tile aliases As/Bs (only used after mainloop's final sync).
__global__ __launch_bounds__(256)
void gemm_tf32(const float* __restrict__ A,
               const float* __restrict__ Wa, const float* __restrict__ Wb,
               const float* __restrict__ Wc,
               const float* __restrict__ ba, const float* __restrict__ bb,
               const float* __restrict__ bc,
               float* __restrict__ Ca, float* __restrict__ Cb, float* __restrict__ Cc,
               int N, int K, int relu,
               const float* __restrict__ resid,
               const float* __restrict__ lng, const float* __restrict__ lnb)
{
    const float* W    = (blockIdx.z == 0) ? Wa : (blockIdx.z == 1) ? Wb : Wc;
    const float* bias = (blockIdx.z == 0) ? ba : (blockIdx.z == 1) ? bb : bc;
    float*       C    = (blockIdx.z == 0) ? Ca : (blockIdx.z == 1) ? Cb : Cc;

    __shared__ __align__(16) union SmemU {
        struct { float As[2][64][20]; float Bs[2][16][136]; } mm;
        float Ct[64][132];
    } su;

    const int bm = blockIdx.y * 64;
    const int tid = threadIdx.x, warp = tid >> 5, lane = tid & 31;
    const int wm = warp & 1, wn = warp >> 1;
    const int g = lane >> 2, t = lane & 3;

    const int ra = tid >> 2,  ca = (tid & 3) * 4;
    const int rb = tid >> 5,  cb = (tid & 31) * 4;

    float acc[2][4][4] = {};

    const int niter = K >> 4;
    cp_async16(&su.mm.As[0][ra][ca],   A + (size_t)(bm + ra) * K + ca);
    cp_async16(&su.mm.Bs[0][rb][cb],   W + (size_t)rb * N + cb);
    cp_async16(&su.mm.Bs[0][rb+8][cb], W + (size_t)(rb + 8) * N + cb);
    asm volatile("cp.async.commit_group;\n");

    for (int it = 0; it < niter; it++) {
        const int cur = it & 1;
        if (it + 1 < niter) {
            const int nxt = cur ^ 1, k0 = (it + 1) << 4;
            cp_async16(&su.mm.As[nxt][ra][ca],   A + (size_t)(bm + ra) * K + k0 + ca);
            cp_async16(&su.mm.Bs[nxt][rb][cb],   W + (size_t)(k0 + rb) * N + cb);
            cp_async16(&su.mm.Bs[nxt][rb+8][cb], W + (size_t)(k0 + rb + 8) * N + cb);
            asm volatile("cp.async.commit_group;\n");
            asm volatile("cp.async.wait_group 1;\n");
        } else {
            asm volatile("cp.async.wait_group 0;\n");
        }
        __syncthreads();

        #pragma unroll
        for (int kk = 0; kk < 16; kk += 8) {
            unsigned a[2][4], bfr[4][2];
            #pragma unroll
            for (int i = 0; i < 2; i++) {
                int row = wm*32 + i*16 + g;
                a[i][0] = f2tf(su.mm.As[cur][row    ][kk + t    ]);
                a[i][1] = f2tf(su.mm.As[cur][row + 8][kk + t    ]);
                a[i][2] = f2tf(su.mm.As[cur][row    ][kk + t + 4]);
                a[i][3] = f2tf(su.mm.As[cur][row + 8][kk + t + 4]);
            }
            #pragma unroll
            for (int j = 0; j < 4; j++) {
                int col = wn*32 + j*8 + g;
                bfr[j][0] = f2tf(su.mm.Bs[cur][kk + t    ][col]);
                bfr[j][1] = f2tf(su.mm.Bs[cur][kk + t + 4][col]);
            }
            #pragma unroll
            for (int i = 0; i < 2; i++)
                #pragma unroll
                for (int j = 0; j < 4; j++)
                    mma_tf32(acc[i][j], a[i], bfr[j]);
        }
        __syncthreads();
    }

    if (resid == nullptr) {
        // plain epilogue: C = (relu?)(acc + bias)
        #pragma unroll
        for (int i = 0; i < 2; i++) {
            #pragma unroll
            for (int half = 0; half < 2; half++) {
                int r = bm + wm*32 + i*16 + g + half*8;
                #pragma unroll
                for (int j = 0; j < 4; j++) {
                    int n0 = wn*32 + j*8 + 2*t;
                    float d0 = acc[i][j][half*2]     + bias[n0];
                    float d1 = acc[i][j][half*2 + 1] + bias[n0 + 1];
                    if (relu) { d0 = fmaxf(d0, 0.f); d1 = fmaxf(d1, 0.f); }
                    C[(size_t)r*N + n0]     = d0;
                    C[(size_t)r*N + n0 + 1] = d1;
                }
            }
        }
    } else {
        // fused epilogue: C = LayerNorm(resid + acc + bias)
        #pragma unroll
        for (int i = 0; i < 2; i++) {
            #pragma unroll
            for (int half = 0; half < 2; half++) {
                int rl = wm*32 + i*16 + g + half*8;
                int rg = bm + rl;
                #pragma unroll
                for (int j = 0; j < 4; j++) {
                    int n0 = wn*32 + j*8 + 2*t;
                    su.Ct[rl][n0]     = acc[i][j][half*2]     + bias[n0]
                                        + resid[(size_t)rg*N + n0];
                    su.Ct[rl][n0 + 1] = acc[i][j][half*2 + 1] + bias[n0 + 1]
                                        + resid[(size_t)rg*N + n0 + 1];
                }
            }
        }
        __syncthreads();
        // warp per 8 rows: LN over 128 cols
        #pragma unroll
        for (int rr = 0; rr < 8; rr++) {
            int rl = warp*8 + rr;
            float v0 = su.Ct[rl][lane];
            float v1 = su.Ct[rl][lane + 32];
            float v2 = su.Ct[rl][lane + 64];
            float v3 = su.Ct[rl][lane + 96];
            float s = v0 + v1 + v2 + v3;
            #pragma unroll
            for (int off = 16; off > 0; off >>= 1)
                s += __shfl_xor_sync(0xffffffffu, s, off);
            float mu = s * (1.f/128.f);
            float d0 = v0 - mu, d1 = v1 - mu, d2 = v2 - mu, d3 = v3 - mu;
            float s2 = d0*d0 + d1*d1 + d2*d2 + d3*d3;
            #pragma unroll
            for (int off = 16; off > 0; off >>= 1)
                s2 += __shfl_xor_sync(0xffffffffu, s2, off);
            float inv = rsqrtf(s2 * (1.f/128.f) + 1e-5f);
            size_t base = (size_t)(bm + rl) * N;
            C[base + lane]      = d0 * inv * lng[lane]      + lnb[lane];
            C[base + lane + 32] = d1 * inv * lng[lane + 32] + lnb[lane + 32];
            C[base + lane + 64] = d2 * inv * lng[lane + 64] + lnb[lane + 64];
            C[base + lane + 96] = d3 * inv * lng[lane + 96] + lnb[lane + 96];
        }
    }
}

// ---------------- Head GEMM (small M, fp32) --------------------------------
__global__ __launch_bounds__(128)
void head_gemm(const float* __restrict__ A, const float* __restrict__ W,
               const float* __restrict__ bias, float* __restrict__ C,
               int M, int N, int K, int relu)
{
    __shared__ __align__(16) float As[8][128];
    const int bn = blockIdx.x * 128, bm = blockIdx.y * 8;
    const int tid = threadIdx.x;
    const int n = bn + tid;
    float acc[8] = {};
    for (int k0 = 0; k0 < K; k0 += 128) {
        int kc = min(128, K - k0);
        #pragma unroll
        for (int i = 0; i < 8; i++)
            As[i][tid] = (tid < kc) ? A[(size_t)(bm + i)*K + k0 + tid] : 0.f;
        __syncthreads();
        if (n < N) {
            for (int k = 0; k < kc; k += 4) {
                float w0 = W[(size_t)(k0 + k    )*N + n];
                float w1 = W[(size_t)(k0 + k + 1)*N + n];
                float w2 = W[(size_t)(k0 + k + 2)*N + n];
                float w3 = W[(size_t)(k0 + k + 3)*N + n];
                #pragma unroll
                for (int i = 0; i < 8; i++) {
                    float4 a = *reinterpret_cast<const float4*>(&As[i][k]);
                    acc[i] += a.x*w0 + a.y*w1 + a.z*w2 + a.w*w3;
                }
            }
        }
        __syncthreads();
    }
    if (n < N) {
        #pragma unroll
        for (int i = 0; i < 8; i++) {
            float v = acc[i] + bias[n];
            if (relu) v = fmaxf(v, 0.f);
            C[(size_t)(bm + i)*N + n] = v;
        }
    }
}

// ---------------- Embedding: warp per bag, float4 (R12 proven version) -----
__global__ void embed_kernel(const int* __restrict__ cat_arr,
                             const int* __restrict__ amt_arr,
                             const int* __restrict__ dt_arr,
                             const float4* __restrict__ cat4,
                             const float4* __restrict__ amt4,
                             const float4* __restrict__ dt4,
                             float4* __restrict__ x4)
{
    int tid = threadIdx.x, w = tid >> 5, lane = tid & 31;
    int bag = blockIdx.x * 4 + w;
    __shared__ int sc[4][64];
    __shared__ int sa[4][64];
    sc[w][lane]      = cat_arr[(size_t)bag*JJ + lane];
    sc[w][lane + 32] = cat_arr[(size_t)bag*JJ + lane + 32];
    sa[w][lane]      = amt_arr[(size_t)bag*JJ + lane];
    sa[w][lane + 32] = amt_arr[(size_t)bag*JJ + lane + 32];
    __syncwarp();
    float4 acc = make_float4(0.f, 0.f, 0.f, 0.f);
    #pragma unroll 4
    for (int j = 0; j < JJ; j++) {
        int c = sc[w][j];
        if (c != CATN) {
            float4 u = __ldg(&cat4[(size_t)c*32 + lane]);
            float4 v = __ldg(&amt4[(size_t)sa[w][j]*32 + lane]);
            acc.x += u.x + v.x; acc.y += u.y + v.y;
            acc.z += u.z + v.z; acc.w += u.w + v.w;
        }
    }
    float4 d = __ldg(&dt4[(size_t)dt_arr[bag]*32 + lane]);
    acc.x += d.x; acc.y += d.y; acc.z += d.z; acc.w += d.w;
    int b = bag >> 7, l = bag & 127;
    x4[((size_t)b*SS + l + 1)*32 + lane] = acc;
}

__global__ void id_kernel(const int* __restrict__ id_arr,
                          const float* __restrict__ id_tab)
{
    int b = blockIdx.x, e = threadIdx.x;
    g_x[(size_t)b*SS*EE + e] = id_tab[(size_t)id_arr[b]*EE + e];
}

// ---------------- Fused tensor-core attention v3 (single-pass tf32) --------
__global__ __launch_bounds__(256)
void attn_mma(const float* __restrict__ q, const float* __restrict__ k,
              const float* __restrict__ v, float* __restrict__ o)
{
    extern __shared__ float smem[];
    float* sS  = smem;
    float* sKT = smem + SS_FLOATS;
    float* sU  = sKT + SKT_FLOATS;

    const int blk = blockIdx.x;
    const int chunk = blk % NCHUNK;
    const int bh = blk / NCHUNK;
    const int b = bh >> 1, h = bh & 1;
    const int row0 = chunk * MCH;

    const int tid = threadIdx.x, wid = tid >> 5, lane = tid & 31;
    const int g = lane >> 2, t = lane & 3;

    {
        float* sQ = sU;
        for (int idx = tid; idx < MCH*16; idx += 256) {
            int r = idx >> 4, dc = (idx & 15) * 4;
            int i = row0 + r;
            float4 tq = make_float4(0.f, 0.f, 0.f, 0.f);
            if (i < SS)
                tq = *reinterpret_cast<const float4*>(&q[((size_t)b*SS + i)*EE + h*HD + dc]);
            sQ[r*QP + dc    ] = rnd_tf(tq.x);
            sQ[r*QP + dc + 1] = rnd_tf(tq.y);
            sQ[r*QP + dc + 2] = rnd_tf(tq.z);
            sQ[r*QP + dc + 3] = rnd_tf(tq.w);
        }
    }
    for (int idx = tid; idx < SS*16; idx += 256) {
        int j = idx >> 4, dc = (idx & 15) * 4;
        float4 tk = *reinterpret_cast<const float4*>(&k[((size_t)b*SS + j)*EE + h*HD + dc]);
        sKT[(dc    )*KTP + j] = rnd_tf(tk.x);
        sKT[(dc + 1)*KTP + j] = rnd_tf(tk.y);
        sKT[(dc + 2)*KTP + j] = rnd_tf(tk.z);
        sKT[(dc + 3)*KTP + j] = rnd_tf(tk.w);
    }
    for (int idx = tid; idx < 64*(SPN - SS); idx += 256) {
        int d = idx / (SPN - SS), j = SS + idx % (SPN - SS);
        sKT[d*KTP + j] = 0.f;
    }
    __syncthreads();

    {
        const float* sQ = sU;
        for (int tile = wid; tile < 3*17; tile += 8) {
            int tm = tile / 17, tn = tile % 17;
            int r0 = tm*16 + g, col = tn*8 + g;
            float acc[4] = {0.f, 0.f, 0.f, 0.f};
            #pragma unroll
            for (int ks = 0; ks < 8; ks++) {
                int kk = ks * 8;
                unsigned a[4], bfr[2];
                a[0] = __float_as_uint(sQ[(r0    )*QP + kk + t    ]);
                a[1] = __float_as_uint(sQ[(r0 + 8)*QP + kk + t    ]);
                a[2] = __float_as_uint(sQ[(r0    )*QP + kk + t + 4]);
                a[3] = __float_as_uint(sQ[(r0 + 8)*QP + kk + t + 4]);
                bfr[0] = __float_as_uint(sKT[(kk + t    )*KTP + col]);
                bfr[1] = __float_as_uint(sKT[(kk + t + 4)*KTP + col]);
                mma_tf32(acc, a, bfr);
            }
            int c0 = tn*8 + 2*t;
            sS[(r0    )*SSP + c0    ] = acc[0] * 0.125f;
            sS[(r0    )*SSP + c0 + 1] = acc[1] * 0.125f;
            sS[(r0 + 8)*SSP + c0    ] = acc[2] * 0.125f;
            sS[(r0 + 8)*SSP + c0 + 1] = acc[3] * 0.125f;
        }
    }
    __syncthreads();

    for (int r = wid; r < MCH; r += 8) {
        int i = row0 + r;
        if (i < SS) {
            float pr[5];
            float mx = -1e30f;
            #pragma unroll
            for (int m = 0; m < 5; m++) {
                int j = lane + m*32;
                float s = (j < SS) ? sS[r*SSP + j] : -1e30f;
                pr[m] = s;
                mx = fmaxf(mx, s);
            }
            #pragma unroll
            for (int off = 16; off > 0; off >>= 1)
                mx = fmaxf(mx, __shfl_xor_sync(0xffffffffu, mx, off));
            float sum = 0.f;
            #pragma unroll
            for (int m = 0; m < 5; m++) {
                int j = lane + m*32;
                float e = (j < SS) ? __expf(pr[m] - mx) : 0.f;
                pr[m] = e; sum += e;
            }
            #pragma unroll
            for (int off = 16; off > 0; off >>= 1)
                sum += __shfl_xor_sync(0xffffffffu, sum, off);
            float inv = 1.f / sum;
            #pragma unroll
            for (int m = 0; m < 5; m++) {
                int j = lane + m*32;
                if (j < SPN)
                    sS[r*SSP + j] = (j < SS) ? rnd_tf(pr[m] * inv) : 0.f;
            }
        } else {
            #pragma unroll
            for (int m = 0; m < 5; m++) {
                int j = lane + m*32;
                if (j < SPN) sS[r*SSP + j] = 0.f;
            }
        }
    }
    {
        float* sV = sU;
        for (int idx = tid; idx < SPN*16; idx += 256) {
            int j = idx >> 4, dc = (idx & 15) * 4;
            float4 tv = make_float4(0.f, 0.f, 0.f, 0.f);
            if (j < SS)
                tv = *reinterpret_cast<const float4*>(&v[((size_t)b*SS + j)*EE + h*HD + dc]);
            sV[j*VP + dc    ] = rnd_tf(tv.x);
            sV[j*VP + dc + 1] = rnd_tf(tv.y);
            sV[j*VP + dc + 2] = rnd_tf(tv.z);
            sV[j*VP + dc + 3] = rnd_tf(tv.w);
        }
    }
    __syncthreads();

    {
        const float* sV = sU;
        for (int tile = wid; tile < 3*8; tile += 8) {
            int tm = tile >> 3, tn = tile & 7;
            int r0 = tm*16 + g, col = tn*8 + g;
            float acc[4] = {0.f, 0.f, 0.f, 0.f};
            #pragma unroll
            for (int ks = 0; ks < 17; ks++) {
                int kk = ks * 8;
                unsigned a[4], bfr[2];
                a[0] = __float_as_uint(sS[(r0    )*SSP + kk + t    ]);
                a[1] = __float_as_uint(sS[(r0 + 8)*SSP + kk + t    ]);
                a[2] = __float_as_uint(sS[(r0    )*SSP + kk + t + 4]);
                a[3] = __float_as_uint(sS[(r0 + 8)*SSP + kk + t + 4]);
                bfr[0] = __float_as_uint(sV[(kk + t    )*VP + col]);
                bfr[1] = __float_as_uint(sV[(kk + t + 4)*VP + col]);
                mma_tf32(acc, a, bfr);
            }
            int c0 = tn*8 + 2*t;
            int i0 = row0 + tm*16 + g;
            if (i0 < SS) {
                float* orow = &o[((size_t)b*SS + i0)*EE + h*HD];
                orow[c0] = acc[0]; orow[c0 + 1] = acc[1];
            }
            if (i0 + 8 < SS) {
                float* orow = &o[((size_t)b*SS + i0 + 8)*EE + h*HD];
                orow[c0] = acc[2]; orow[c0 + 1] = acc[3];
            }
        }
    }
}

// ---------------- Mean pool ----------------
__global__ void pool_kernel(const float* __restrict__ x, float* __restrict__ h)
{
    int b = blockIdx.x, e = threadIdx.x;
    float s = 0.f;
    #pragma unroll 4
    for (int l = 1; l <= LL; l++) s += x[((size_t)b*SS + l)*EE + e];
    h[(size_t)b*EE + e] = s * (1.f/128.f);
}

// ---------------- Launch ----------------
extern "C" void kernel_launch(void* const* d_in, const int* in_sizes, int n_in,
                              void* d_out, int out_size)
{
    (void)in_sizes; (void)n_in; (void)out_size;
    const int*   cat_arr = (const int*)  d_in[0];
    const int*   dt_arr  = (const int*)  d_in[1];
    const int*   amt_arr = (const int*)  d_in[2];
    const int*   id_arr  = (const int*)  d_in[3];
    const float* id_tab  = (const float*)d_in[4];
    const float* cat_tab = (const float*)d_in[5];
    const float* amt_tab = (const float*)d_in[6];
    const float* dt_tab  = (const float*)d_in[7];
    const float* Wq = (const float*)d_in[8],  *bq = (const float*)d_in[9];
    const float* Wk = (const float*)d_in[10], *bk = (const float*)d_in[11];
    const float* Wv = (const float*)d_in[12], *bv = (const float*)d_in[13];
    const float* Wo = (const float*)d_in[14], *bo = (const float*)d_in[15];
    const float* ln1g = (const float*)d_in[16], *ln1b = (const float*)d_in[17];
    const float* W1 = (const float*)d_in[18], *b1 = (const float*)d_in[19];
    const float* W2 = (const float*)d_in[20], *b2 = (const float*)d_in[21];
    const float* ln2g = (const float*)d_in[22], *ln2b = (const float*)d_in[23];
    const float* l1W = (const float*)d_in[24], *l1b = (const float*)d_in[25];
    const float* l2W = (const float*)d_in[26], *l2b = (const float*)d_in[27];
    float* out = (float*)d_out;

    float *x, *q, *k, *v, *o, *f1, *h, *x1;
    cudaGetSymbolAddress((void**)&x,   g_x);
    cudaGetSymbolAddress((void**)&q,   g_q);
    cudaGetSymbolAddress((void**)&k,   g_k);
    cudaGetSymbolAddress((void**)&v,   g_v);
    cudaGetSymbolAddress((void**)&o,   g_o);
    cudaGetSymbolAddress((void**)&f1,  g_f1);
    cudaGetSymbolAddress((void**)&h,   g_h);
    cudaGetSymbolAddress((void**)&x1,  g_x1);

    static int attn_smem_set = 0;
    if (!attn_smem_set) {
        cudaFuncSetAttribute(attn_mma,
                             cudaFuncAttributeMaxDynamicSharedMemorySize,
                             ATTN_SMEM_BYTES);
        attn_smem_set = 1;
    }

    // 1. embeddings (proven R12 kernel)
    embed_kernel<<<BB*LL/4, 128>>>(cat_arr, amt_arr, dt_arr,
                                   (const float4*)cat_tab, (const float4*)amt_tab,
                                   (const float4*)dt_tab, (float4*)x);
    id_kernel<<<BB, EE>>>(id_arr, id_tab);

    // 2. QKV: one batched launch (z = 0,1,2)
    dim3 gQKV(1, ROWS/64, 3);
    gemm_tf32<<<gQKV, 256>>>(x, Wq, Wk, Wv, bq, bk, bv, q, k, v, EE, EE, 0,
                             nullptr, nullptr, nullptr);

    // 3. fused tensor-core attention (single-pass tf32)
    attn_mma<<<BB*HH*NCHUNK, 256, ATTN_SMEM_BYTES>>>(q, k, v, o);

    // 4. out proj + fused residual + LN1:  x = LN(x + o@Wo + bo)
    dim3 g1(1, ROWS/64, 1);
    gemm_tf32<<<g1, 256>>>(o, Wo, Wo, Wo, bo, bo, bo, x, x, x, EE, EE, 0,
                           x, ln1g, ln1b);

    // 5. FFN:  f1 = relu(x@W1 + b1);  x = LN(x + f1@W2 + b2)
    gemm_tf32<<<g1, 256>>>(x,  W1, W1, W1, b1, b1, b1, f1, f1, f1, EE, EE, 1,
                           nullptr, nullptr, nullptr);
    gemm_tf32<<<g1, 256>>>(f1, W2, W2, W2, b2, b2, b2, x, x, x, EE, EE, 0,
                           x, ln2g, ln2b);

    // 6. pool + classifier head
    pool_kernel<<<BB, EE>>>(x, h);
    dim3 gH1((CATN + 127)/128, BB/8);
    head_gemm<<<gH1, 128>>>(h,  l1W, l1b, x1,  BB, CATN, EE,   1);
    head_gemm<<<gH1, 128>>>(x1, l2W, l2b, out, BB, CATN, CATN, 0);
}

// round 16
// speedup vs baseline: 2.0794x; 1.0138x over previous
#include <cuda_runtime.h>
#include <math.h>

// ---------------- Problem constants ----------------
#define BB   128
#define LL   128
#define JJ   64
#define EE   128
#define SS   129
#define HH   2
#define HD   64
#define CATN 1000
#define ROWS (BB*SS)   // 16512 = 258 * 64

// ---------------- fused mma-attention geometry (v4) ------------------------
#define MCH    48
#define NCHUNK 3
#define SPN    136
#define SSP    140
#define KTP    136
#define VP     72
#define QP     68
#define ATH    384            // attn threads (12 warps)
#define AW     12
#define SS_FLOATS   (MCH*SSP)
#define SKT_FLOATS  (64*KTP)
#define SUN_FLOATS  (SPN*VP)
#define ATTN_SMEM_BYTES ((SS_FLOATS + SKT_FLOATS + SUN_FLOATS) * 4)  // 100864

// ---------------- Device scratch ----------------
__device__ float g_x  [ROWS*EE];
__device__ float g_q  [ROWS*EE];
__device__ float g_k  [ROWS*EE];
__device__ float g_v  [ROWS*EE];
__device__ float g_o  [ROWS*EE];
__device__ float g_f1 [ROWS*EE];
__device__ float g_h  [BB*EE];
__device__ float g_x1 [BB*CATN];

// ---------------- TF32 / cp.async helpers ----------------
__device__ __forceinline__ unsigned f2tf(float x) {
    unsigned u;
    asm("cvt.rna.tf32.f32 %0, %1;" : "=r"(u) : "f"(x));
    return u;
}
__device__ __forceinline__ float rnd_tf(float x) {
    return __uint_as_float(f2tf(x));
}
__device__ __forceinline__ void mma_tf32(float* d, const unsigned* a, const unsigned* b) {
    asm volatile(
        "mma.sync.aligned.m16n8k8.row.col.f32.tf32.tf32.f32 "
        "{%0,%1,%2,%3}, {%4,%5,%6,%7}, {%8,%9}, {%0,%1,%2,%3};\n"
        : "+f"(d[0]), "+f"(d[1]), "+f"(d[2]), "+f"(d[3])
        : "r"(a[0]), "r"(a[1]), "r"(a[2]), "r"(a[3]), "r"(b[0]), "r"(b[1]));
}
__device__ __forceinline__ void cp_async16(void* smem, const void* gmem) {
    unsigned s = (unsigned)__cvta_generic_to_shared(smem);
    asm volatile("cp.async.ca.shared.global [%0], [%1], 16;\n" :: "r"(s), "l"(gmem));
}

// ---------------- Single-pass TF32 GEMM, 64x128 tile, BK=16, cp.async ------
// Optional fused epilogue: out = LayerNorm(resid + (A@W + bias)).
__global__ __launch_bounds__(256)
void gemm_tf32(const float* __restrict__ A,
               const float* __restrict__ Wa, const float* __restrict__ Wb,
               const float* __restrict__ Wc,
               const float* __restrict__ ba, const float* __restrict__ bb,
               const float* __restrict__ bc,
               float* __restrict__ Ca, float* __restrict__ Cb, float* __restrict__ Cc,
               int N, int K, int relu,
               const float* __restrict__ resid,
               const float* __restrict__ lng, const float* __restrict__ lnb)
{
    const float* W    = (blockIdx.z == 0) ? Wa : (blockIdx.z == 1) ? Wb : Wc;
    const float* bias = (blockIdx.z == 0) ? ba : (blockIdx.z == 1) ? bb : bc;
    float*       C    = (blockIdx.z == 0) ? Ca : (blockIdx.z == 1) ? Cb : Cc;

    __shared__ __align__(16) union SmemU {
        struct { float As[2][64][20]; float Bs[2][16][136]; } mm;
        float Ct[64][132];
    } su;

    const int bm = blockIdx.y * 64;
    const int tid = threadIdx.x, warp = tid >> 5, lane = tid & 31;
    const int wm = warp & 1, wn = warp >> 1;
    const int g = lane >> 2, t = lane & 3;

    const int ra = tid >> 2,  ca = (tid & 3) * 4;
    const int rb = tid >> 5,  cb = (tid & 31) * 4;

    float acc[2][4][4] = {};

    const int niter = K >> 4;
    cp_async16(&su.mm.As[0][ra][ca],   A + (size_t)(bm + ra) * K + ca);
    cp_async16(&su.mm.Bs[0][rb][cb],   W + (size_t)rb * N + cb);
    cp_async16(&su.mm.Bs[0][rb+8][cb], W + (size_t)(rb + 8) * N + cb);
    asm volatile("cp.async.commit_group;\n");

    for (int it = 0; it < niter; it++) {
        const int cur = it & 1;
        if (it + 1 < niter) {
            const int nxt = cur ^ 1, k0 = (it + 1) << 4;
            cp_async16(&su.mm.As[nxt][ra][ca],   A + (size_t)(bm + ra) * K + k0 + ca);
            cp_async16(&su.mm.Bs[nxt][rb][cb],   W + (size_t)(k0 + rb) * N + cb);
            cp_async16(&su.mm.Bs[nxt][rb+8][cb], W + (size_t)(k0 + rb + 8) * N + cb);
            asm volatile("cp.async.commit_group;\n");
            asm volatile("cp.async.wait_group 1;\n");
        } else {
            asm volatile("cp.async.wait_group 0;\n");
        }
        __syncthreads();

        #pragma unroll
        for (int kk = 0; kk < 16; kk += 8) {
            unsigned a[2][4], bfr[4][2];
            #pragma unroll
            for (int i = 0; i < 2; i++) {
                int row = wm*32 + i*16 + g;
                a[i][0] = f2tf(su.mm.As[cur][row    ][kk + t    ]);
                a[i][1] = f2tf(su.mm.As[cur][row + 8][kk + t    ]);
                a[i][2] = f2tf(su.mm.As[cur][row    ][kk + t + 4]);
                a[i][3] = f2tf(su.mm.As[cur][row + 8][kk + t + 4]);
            }
            #pragma unroll
            for (int j = 0; j < 4; j++) {
                int col = wn*32 + j*8 + g;
                bfr[j][0] = f2tf(su.mm.Bs[cur][kk + t    ][col]);
                bfr[j][1] = f2tf(su.mm.Bs[cur][kk + t + 4][col]);
            }
            #pragma unroll
            for (int i = 0; i < 2; i++)
                #pragma unroll
                for (int j = 0; j < 4; j++)
                    mma_tf32(acc[i][j], a[i], bfr[j]);
        }
        __syncthreads();
    }

    if (resid == nullptr) {
        #pragma unroll
        for (int i = 0; i < 2; i++) {
            #pragma unroll
            for (int half = 0; half < 2; half++) {
                int r = bm + wm*32 + i*16 + g + half*8;
                #pragma unroll
                for (int j = 0; j < 4; j++) {
                    int n0 = wn*32 + j*8 + 2*t;
                    float d0 = acc[i][j][half*2]     + bias[n0];
                    float d1 = acc[i][j][half*2 + 1] + bias[n0 + 1];
                    if (relu) { d0 = fmaxf(d0, 0.f); d1 = fmaxf(d1, 0.f); }
                    C[(size_t)r*N + n0]     = d0;
                    C[(size_t)r*N + n0 + 1] = d1;
                }
            }
        }
    } else {
        // fused: C = LayerNorm(resid + acc + bias)
        #pragma unroll
        for (int i = 0; i < 2; i++) {
            #pragma unroll
            for (int half = 0; half < 2; half++) {
                int rl = wm*32 + i*16 + g + half*8;
                int rg = bm + rl;
                #pragma unroll
                for (int j = 0; j < 4; j++) {
                    int n0 = wn*32 + j*8 + 2*t;
                    su.Ct[rl][n0]     = acc[i][j][half*2]     + bias[n0]
                                        + resid[(size_t)rg*N + n0];
                    su.Ct[rl][n0 + 1] = acc[i][j][half*2 + 1] + bias[n0 + 1]
                                        + resid[(size_t)rg*N + n0 + 1];
                }
            }
        }
        __syncthreads();
        #pragma unroll
        for (int rr = 0; rr < 8; rr++) {
            int rl = warp*8 + rr;
            float v0 = su.Ct[rl][lane];
            float v1 = su.Ct[rl][lane + 32];
            float v2 = su.Ct[rl][lane + 64];
            float v3 = su.Ct[rl][lane + 96];
            float s = v0 + v1 + v2 + v3;
            #pragma unroll
            for (int off = 16; off > 0; off >>= 1)
                s += __shfl_xor_sync(0xffffffffu, s, off);
            float mu = s * (1.f/128.f);
            float d0 = v0 - mu, d1 = v1 - mu, d2 = v2 - mu, d3 = v3 - mu;
            float s2 = d0*d0 + d1*d1 + d2*d2 + d3*d3;
            #pragma unroll
            for (int off = 16; off > 0; off >>= 1)
                s2 += __shfl_xor_sync(0xffffffffu, s2, off);
            float inv = rsqrtf(s2 * (1.f/128.f) + 1e-5f);
            size_t base = (size_t)(bm + rl) * N;
            C[base + lane]      = d0 * inv * lng[lane]      + lnb[lane];
            C[base + lane + 32] = d1 * inv * lng[lane + 32] + lnb[lane + 32];
            C[base + lane + 64] = d2 * inv * lng[lane + 64] + lnb[lane + 64];
            C[base + lane + 96] = d3 * inv * lng[lane + 96] + lnb[lane + 96];
        }
    }
}

// ---------------- Head GEMM (small M, fp32) --------------------------------
__global__ __launch_bounds__(128)
void head_gemm(const float* __restrict__ A, const float* __restrict__ W,
               const float* __restrict__ bias, float* __restrict__ C,
               int M, int N, int K, int relu)
{
    __shared__ __align__(16) float As[8][128];
    const int bn = blockIdx.x * 128, bm = blockIdx.y * 8;
    const int tid = threadIdx.x;
    const int n = bn + tid;
    float acc[8] = {};
    for (int k0 = 0; k0 < K; k0 += 128) {
        int kc = min(128, K - k0);
        #pragma unroll
        for (int i = 0; i < 8; i++)
            As[i][tid] = (tid < kc) ? A[(size_t)(bm + i)*K + k0 + tid] : 0.f;
        __syncthreads();
        if (n < N) {
            for (int k = 0; k < kc; k += 4) {
                float w0 = W[(size_t)(k0 + k    )*N + n];
                float w1 = W[(size_t)(k0 + k + 1)*N + n];
                float w2 = W[(size_t)(k0 + k + 2)*N + n];
                float w3 = W[(size_t)(k0 + k + 3)*N + n];
                #pragma unroll
                for (int i = 0; i < 8; i++) {
                    float4 a = *reinterpret_cast<const float4*>(&As[i][k]);
                    acc[i] += a.x*w0 + a.y*w1 + a.z*w2 + a.w*w3;
                }
            }
        }
        __syncthreads();
    }
    if (n < N) {
        #pragma unroll
        for (int i = 0; i < 8; i++) {
            float v = acc[i] + bias[n];
            if (relu) v = fmaxf(v, 0.f);
            C[(size_t)(bm + i)*N + n] = v;
        }
    }
}

// ---------------- Embedding: warp per bag, float4 (proven) -----------------
__global__ void embed_kernel(const int* __restrict__ cat_arr,
                             const int* __restrict__ amt_arr,
                             const int* __restrict__ dt_arr,
                             const float4* __restrict__ cat4,
                             const float4* __restrict__ amt4,
                             const float4* __restrict__ dt4,
                             float4* __restrict__ x4)
{
    int tid = threadIdx.x, w = tid >> 5, lane = tid & 31;
    int bag = blockIdx.x * 4 + w;
    __shared__ int sc[4][64];
    __shared__ int sa[4][64];
    sc[w][lane]      = cat_arr[(size_t)bag*JJ + lane];
    sc[w][lane + 32] = cat_arr[(size_t)bag*JJ + lane + 32];
    sa[w][lane]      = amt_arr[(size_t)bag*JJ + lane];
    sa[w][lane + 32] = amt_arr[(size_t)bag*JJ + lane + 32];
    __syncwarp();
    float4 acc = make_float4(0.f, 0.f, 0.f, 0.f);
    #pragma unroll 4
    for (int j = 0; j < JJ; j++) {
        int c = sc[w][j];
        if (c != CATN) {
            float4 u = __ldg(&cat4[(size_t)c*32 + lane]);
            float4 v = __ldg(&amt4[(size_t)sa[w][j]*32 + lane]);
            acc.x += u.x + v.x; acc.y += u.y + v.y;
            acc.z += u.z + v.z; acc.w += u.w + v.w;
        }
    }
    float4 d = __ldg(&dt4[(size_t)dt_arr[bag]*32 + lane]);
    acc.x += d.x; acc.y += d.y; acc.z += d.z; acc.w += d.w;
    int b = bag >> 7, l = bag & 127;
    x4[((size_t)b*SS + l + 1)*32 + lane] = acc;
}

__global__ void id_kernel(const int* __restrict__ id_arr,
                          const float* __restrict__ id_tab)
{
    int b = blockIdx.x, e = threadIdx.x;
    g_x[(size_t)b*SS*EE + e] = id_tab[(size_t)id_arr[b]*EE + e];
}

// ---------------- Fused tensor-core attention v4 ----------------
// Single-pass tf32; 12 warps; dual (even/odd k-step) accumulators to halve
// the serial MMA dependency chain.
__global__ __launch_bounds__(ATH)
void attn_mma(const float* __restrict__ q, const float* __restrict__ k,
              const float* __restrict__ v, float* __restrict__ o)
{
    extern __shared__ float smem[];
    float* sS  = smem;
    float* sKT = smem + SS_FLOATS;
    float* sU  = sKT + SKT_FLOATS;

    const int blk = blockIdx.x;
    const int chunk = blk % NCHUNK;
    const int bh = blk / NCHUNK;
    const int b = bh >> 1, h = bh & 1;
    const int row0 = chunk * MCH;

    const int tid = threadIdx.x, wid = tid >> 5, lane = tid & 31;
    const int g = lane >> 2, t = lane & 3;

    // ---- load Q rounded to tf32 ----
    {
        float* sQ = sU;
        for (int idx = tid; idx < MCH*16; idx += ATH) {
            int r = idx >> 4, dc = (idx & 15) * 4;
            int i = row0 + r;
            float4 tq = make_float4(0.f, 0.f, 0.f, 0.f);
            if (i < SS)
                tq = *reinterpret_cast<const float4*>(&q[((size_t)b*SS + i)*EE + h*HD + dc]);
            sQ[r*QP + dc    ] = rnd_tf(tq.x);
            sQ[r*QP + dc + 1] = rnd_tf(tq.y);
            sQ[r*QP + dc + 2] = rnd_tf(tq.z);
            sQ[r*QP + dc + 3] = rnd_tf(tq.w);
        }
    }
    // ---- load K^T rounded; zero-pad ----
    for (int idx = tid; idx < SS*16; idx += ATH) {
        int j = idx >> 4, dc = (idx & 15) * 4;
        float4 tk = *reinterpret_cast<const float4*>(&k[((size_t)b*SS + j)*EE + h*HD + dc]);
        sKT[(dc    )*KTP + j] = rnd_tf(tk.x);
        sKT[(dc + 1)*KTP + j] = rnd_tf(tk.y);
        sKT[(dc + 2)*KTP + j] = rnd_tf(tk.z);
        sKT[(dc + 3)*KTP + j] = rnd_tf(tk.w);
    }
    for (int idx = tid; idx < 64*(SPN - SS); idx += ATH) {
        int d = idx / (SPN - SS), j = SS + idx % (SPN - SS);
        sKT[d*KTP + j] = 0.f;
    }
    __syncthreads();

    // ---- Phase 1: scores = Q @ K^T, dual-chain accumulate ----
    {
        const float* sQ = sU;
        for (int tile = wid; tile < 3*17; tile += AW) {
            int tm = tile / 17, tn = tile % 17;
            int r0 = tm*16 + g, col = tn*8 + g;
            float ac0[4] = {0.f, 0.f, 0.f, 0.f};
            float ac1[4] = {0.f, 0.f, 0.f, 0.f};
            #pragma unroll
            for (int ks = 0; ks < 8; ks += 2) {
                int kk0 = ks * 8, kk1 = kk0 + 8;
                unsigned a0[4], b0[2], a1[4], b1[2];
                a0[0] = __float_as_uint(sQ[(r0    )*QP + kk0 + t    ]);
                a0[1] = __float_as_uint(sQ[(r0 + 8)*QP + kk0 + t    ]);
                a0[2] = __float_as_uint(sQ[(r0    )*QP + kk0 + t + 4]);
                a0[3] = __float_as_uint(sQ[(r0 + 8)*QP + kk0 + t + 4]);
                b0[0] = __float_as_uint(sKT[(kk0 + t    )*KTP + col]);
                b0[1] = __float_as_uint(sKT[(kk0 + t + 4)*KTP + col]);
                a1[0] = __float_as_uint(sQ[(r0    )*QP + kk1 + t    ]);
                a1[1] = __float_as_uint(sQ[(r0 + 8)*QP + kk1 + t    ]);
                a1[2] = __float_as_uint(sQ[(r0    )*QP + kk1 + t + 4]);
                a1[3] = __float_as_uint(sQ[(r0 + 8)*QP + kk1 + t + 4]);
                b1[0] = __float_as_uint(sKT[(kk1 + t    )*KTP + col]);
                b1[1] = __float_as_uint(sKT[(kk1 + t + 4)*KTP + col]);
                mma_tf32(ac0, a0, b0);
                mma_tf32(ac1, a1, b1);
            }
            int c0 = tn*8 + 2*t;
            sS[(r0    )*SSP + c0    ] = (ac0[0] + ac1[0]) * 0.125f;
            sS[(r0    )*SSP + c0 + 1] = (ac0[1] + ac1[1]) * 0.125f;
            sS[(r0 + 8)*SSP + c0    ] = (ac0[2] + ac1[2]) * 0.125f;
            sS[(r0 + 8)*SSP + c0 + 1] = (ac0[3] + ac1[3]) * 0.125f;
        }
    }
    __syncthreads();

    // ---- Phase 2: softmax; write P rounded to tf32 ----
    for (int r = wid; r < MCH; r += AW) {
        int i = row0 + r;
        if (i < SS) {
            float pr[5];
            float mx = -1e30f;
            #pragma unroll
            for (int m = 0; m < 5; m++) {
                int j = lane + m*32;
                float s = (j < SS) ? sS[r*SSP + j] : -1e30f;
                pr[m] = s;
                mx = fmaxf(mx, s);
            }
            #pragma unroll
            for (int off = 16; off > 0; off >>= 1)
                mx = fmaxf(mx, __shfl_xor_sync(0xffffffffu, mx, off));
            float sum = 0.f;
            #pragma unroll
            for (int m = 0; m < 5; m++) {
                int j = lane + m*32;
                float e = (j < SS) ? __expf(pr[m] - mx) : 0.f;
                pr[m] = e; sum += e;
            }
            #pragma unroll
            for (int off = 16; off > 0; off >>= 1)
                sum += __shfl_xor_sync(0xffffffffu, sum, off);
            float inv = 1.f / sum;
            #pragma unroll
            for (int m = 0; m < 5; m++) {
                int j = lane + m*32;
                if (j < SPN)
                    sS[r*SSP + j] = (j < SS) ? rnd_tf(pr[m] * inv) : 0.f;
            }
        } else {
            #pragma unroll
            for (int m = 0; m < 5; m++) {
                int j = lane + m*32;
                if (j < SPN) sS[r*SSP + j] = 0.f;
            }
        }
    }
    // ---- load V rounded into union ----
    {
        float* sV = sU;
        for (int idx = tid; idx < SPN*16; idx += ATH) {
            int j = idx >> 4, dc = (idx & 15) * 4;
            float4 tv = make_float4(0.f, 0.f, 0.f, 0.f);
            if (j < SS)
                tv = *reinterpret_cast<const float4*>(&v[((size_t)b*SS + j)*EE + h*HD + dc]);
            sV[j*VP + dc    ] = rnd_tf(tv.x);
            sV[j*VP + dc + 1] = rnd_tf(tv.y);
            sV[j*VP + dc + 2] = rnd_tf(tv.z);
            sV[j*VP + dc + 3] = rnd_tf(tv.w);
        }
    }
    __syncthreads();

    // ---- Phase 3: out = P @ V, dual-chain accumulate (17 = 8 pairs + 1) ----
    {
        const float* sV = sU;
        for (int tile = wid; tile < 3*8; tile += AW) {
            int tm = tile >> 3, tn = tile & 7;
            int r0 = tm*16 + g, col = tn*8 + g;
            float ac0[4] = {0.f, 0.f, 0.f, 0.f};
            float ac1[4] = {0.f, 0.f, 0.f, 0.f};
            #pragma unroll
            for (int ks = 0; ks < 16; ks += 2) {
                int kk0 = ks * 8, kk1 = kk0 + 8;
                unsigned a0[4], b0[2], a1[4], b1[2];
                a0[0] = __float_as_uint(sS[(r0    )*SSP + kk0 + t    ]);
                a0[1] = __float_as_uint(sS[(r0 + 8)*SSP + kk0 + t    ]);
                a0[2] = __float_as_uint(sS[(r0    )*SSP + kk0 + t + 4]);
                a0[3] = __float_as_uint(sS[(r0 + 8)*SSP + kk0 + t + 4]);
                b0[0] = __float_as_uint(sV[(kk0 + t    )*VP + col]);
                b0[1] = __float_as_uint(sV[(kk0 + t + 4)*VP + col]);
                a1[0] = __float_as_uint(sS[(r0    )*SSP + kk1 + t    ]);
                a1[1] = __float_as_uint(sS[(r0 + 8)*SSP + kk1 + t    ]);
                a1[2] = __float_as_uint(sS[(r0    )*SSP + kk1 + t + 4]);
                a1[3] = __float_as_uint(sS[(r0 + 8)*SSP + kk1 + t + 4]);
                b1[0] = __float_as_uint(sV[(kk1 + t    )*VP + col]);
                b1[1] = __float_as_uint(sV[(kk1 + t + 4)*VP + col]);
                mma_tf32(ac0, a0, b0);
                mma_tf32(ac1, a1, b1);
            }
            {   // last k-step (ks = 16)
                int kk = 16 * 8;
                unsigned a[4], bfr[2];
                a[0] = __float_as_uint(sS[(r0    )*SSP + kk + t    ]);
                a[1] = __float_as_uint(sS[(r0 + 8)*SSP + kk + t    ]);
                a[2] = __float_as_uint(sS[(r0    )*SSP + kk + t + 4]);
                a[3] = __float_as_uint(sS[(r0 + 8)*SSP + kk + t + 4]);
                bfr[0] = __float_as_uint(sV[(kk + t    )*VP + col]);
                bfr[1] = __float_as_uint(sV[(kk + t + 4)*VP + col]);
                mma_tf32(ac0, a, bfr);
            }
            int c0 = tn*8 + 2*t;
            int i0 = row0 + tm*16 + g;
            if (i0 < SS) {
                float* orow = &o[((size_t)b*SS + i0)*EE + h*HD];
                orow[c0]     = ac0[0] + ac1[0];
                orow[c0 + 1] = ac0[1] + ac1[1];
            }
            if (i0 + 8 < SS) {
                float* orow = &o[((size_t)b*SS + i0 + 8)*EE + h*HD];
                orow[c0]     = ac0[2] + ac1[2];
                orow[c0 + 1] = ac0[3] + ac1[3];
            }
        }
    }
}

// ---------------- Mean pool ----------------
__global__ void pool_kernel(const float* __restrict__ x, float* __restrict__ h)
{
    int b = blockIdx.x, e = threadIdx.x;
    float s = 0.f;
    #pragma unroll 4
    for (int l = 1; l <= LL; l++) s += x[((size_t)b*SS + l)*EE + e];
    h[(size_t)b*EE + e] = s * (1.f/128.f);
}

// ---------------- Launch ----------------
extern "C" void kernel_launch(void* const* d_in, const int* in_sizes, int n_in,
                              void* d_out, int out_size)
{
    (void)in_sizes; (void)n_in; (void)out_size;
    const int*   cat_arr = (const int*)  d_in[0];
    const int*   dt_arr  = (const int*)  d_in[1];
    const int*   amt_arr = (const int*)  d_in[2];
    const int*   id_arr  = (const int*)  d_in[3];
    const float* id_tab  = (const float*)d_in[4];
    const float* cat_tab = (const float*)d_in[5];
    const float* amt_tab = (const float*)d_in[6];
    const float* dt_tab  = (const float*)d_in[7];
    const float* Wq = (const float*)d_in[8],  *bq = (const float*)d_in[9];
    const float* Wk = (const float*)d_in[10], *bk = (const float*)d_in[11];
    const float* Wv = (const float*)d_in[12], *bv = (const float*)d_in[13];
    const float* Wo = (const float*)d_in[14], *bo = (const float*)d_in[15];
    const float* ln1g = (const float*)d_in[16], *ln1b = (const float*)d_in[17];
    const float* W1 = (const float*)d_in[18], *b1 = (const float*)d_in[19];
    const float* W2 = (const float*)d_in[20], *b2 = (const float*)d_in[21];
    const float* ln2g = (const float*)d_in[22], *ln2b = (const float*)d_in[23];
    const float* l1W = (const float*)d_in[24], *l1b = (const float*)d_in[25];
    const float* l2W = (const float*)d_in[26], *l2b = (const float*)d_in[27];
    float* out = (float*)d_out;

    float *x, *q, *k, *v, *o, *f1, *h, *x1;
    cudaGetSymbolAddress((void**)&x,   g_x);
    cudaGetSymbolAddress((void**)&q,   g_q);
    cudaGetSymbolAddress((void**)&k,   g_k);
    cudaGetSymbolAddress((void**)&v,   g_v);
    cudaGetSymbolAddress((void**)&o,   g_o);
    cudaGetSymbolAddress((void**)&f1,  g_f1);
    cudaGetSymbolAddress((void**)&h,   g_h);
    cudaGetSymbolAddress((void**)&x1,  g_x1);

    static int attn_smem_set = 0;
    if (!attn_smem_set) {
        cudaFuncSetAttribute(attn_mma,
                             cudaFuncAttributeMaxDynamicSharedMemorySize,
                             ATTN_SMEM_BYTES);
        attn_smem_set = 1;
    }

    // 1. embeddings
    embed_kernel<<<BB*LL/4, 128>>>(cat_arr, amt_arr, dt_arr,
                                   (const float4*)cat_tab, (const float4*)amt_tab,
                                   (const float4*)dt_tab, (float4*)x);
    id_kernel<<<BB, EE>>>(id_arr, id_tab);

    // 2. QKV: one batched launch (z = 0,1,2)
    dim3 gQKV(1, ROWS/64, 3);
    gemm_tf32<<<gQKV, 256>>>(x, Wq, Wk, Wv, bq, bk, bv, q, k, v, EE, EE, 0,
                             nullptr, nullptr, nullptr);

    // 3. fused tensor-core attention
    attn_mma<<<BB*HH*NCHUNK, ATH, ATTN_SMEM_BYTES>>>(q, k, v, o);

    // 4. out proj + fused residual + LN1:  x = LN(x + o@Wo + bo)
    dim3 g1(1, ROWS/64, 1);
    gemm_tf32<<<g1, 256>>>(o, Wo, Wo, Wo, bo, bo, bo, x, x, x, EE, EE, 0,
                           x, ln1g, ln1b);

    // 5. FFN:  f1 = relu(x@W1 + b1);  x = LN(x + f1@W2 + b2)
    gemm_tf32<<<g1, 256>>>(x,  W1, W1, W1, b1, b1, b1, f1, f1, f1, EE, EE, 1,
                           nullptr, nullptr, nullptr);
    gemm_tf32<<<g1, 256>>>(f1, W2, W2, W2, b2, b2, b2, x, x, x, EE, EE, 0,
                           x, ln2g, ln2b);

    // 6. pool + classifier head
    pool_kernel<<<BB, EE>>>(x, h);
    dim3 gH1((CATN + 127)/128, BB/8);
    head_gemm<<<gH1, 128>>>(h,  l1W, l1b, x1,  BB, CATN, EE,   1);
    head_gemm<<<gH1, 128>>>(x1, l2W, l2b, out, BB, CATN, CATN, 0);
}

// round 17
// speedup vs baseline: 2.1034x; 1.0116x over previous
#include <cuda_runtime.h>
#include <math.h>

// ---------------- Problem constants ----------------
#define BB   128
#define LL   128
#define JJ   64
#define EE   128
#define SS   129
#define HH   2
#define HD   64
#define CATN 1000
#define ROWS (BB*SS)   // 16512 = 258 * 64

// ---------------- fused mma-attention geometry (v5) ------------------------
#define MCH    48
#define NCHUNK 3
#define SPN    136
#define SSP    140
#define KTP    136
#define VP     72
#define QP     68
#define ATH    384            // attn threads (12 warps)
#define AW     12
#define SS_FLOATS   (MCH*SSP)
#define SKT_FLOATS  (64*KTP)
#define SUN_FLOATS  (SPN*VP)
#define ATTN_SMEM_BYTES ((SS_FLOATS + SKT_FLOATS + SUN_FLOATS) * 4)  // 100864

// ---------------- Device scratch ----------------
__device__ float g_x  [ROWS*EE];
__device__ float g_q  [ROWS*EE];
__device__ float g_k  [ROWS*EE];
__device__ float g_v  [ROWS*EE];
__device__ float g_o  [ROWS*EE];
__device__ float g_f1 [ROWS*EE];
__device__ float g_h  [BB*EE];
__device__ float g_x1 [BB*CATN];

// ---------------- TF32 / cp.async helpers ----------------
__device__ __forceinline__ unsigned f2tf(float x) {
    unsigned u;
    asm("cvt.rna.tf32.f32 %0, %1;" : "=r"(u) : "f"(x));
    return u;
}
__device__ __forceinline__ float rnd_tf(float x) {
    return __uint_as_float(f2tf(x));
}
__device__ __forceinline__ void mma_tf32(float* d, const unsigned* a, const unsigned* b) {
    asm volatile(
        "mma.sync.aligned.m16n8k8.row.col.f32.tf32.tf32.f32 "
        "{%0,%1,%2,%3}, {%4,%5,%6,%7}, {%8,%9}, {%0,%1,%2,%3};\n"
        : "+f"(d[0]), "+f"(d[1]), "+f"(d[2]), "+f"(d[3])
        : "r"(a[0]), "r"(a[1]), "r"(a[2]), "r"(a[3]), "r"(b[0]), "r"(b[1]));
}
__device__ __forceinline__ void cp_async16(void* smem, const void* gmem) {
    unsigned s = (unsigned)__cvta_generic_to_shared(smem);
    asm volatile("cp.async.ca.shared.global [%0], [%1], 16;\n" :: "r"(s), "l"(gmem));
}

// ---------------- Single-pass TF32 GEMM, 64x128 tile, BK=16, cp.async ------
// Optional fused epilogue: out = LayerNorm(resid + (A@W + bias)).
__global__ __launch_bounds__(256)
void gemm_tf32(const float* __restrict__ A,
               const float* __restrict__ Wa, const float* __restrict__ Wb,
               const float* __restrict__ Wc,
               const float* __restrict__ ba, const float* __restrict__ bb,
               const float* __restrict__ bc,
               float* __restrict__ Ca, float* __restrict__ Cb, float* __restrict__ Cc,
               int N, int K, int relu,
               const float* __restrict__ resid,
               const float* __restrict__ lng, const float* __restrict__ lnb)
{
    const float* W    = (blockIdx.z == 0) ? Wa : (blockIdx.z == 1) ? Wb : Wc;
    const float* bias = (blockIdx.z == 0) ? ba : (blockIdx.z == 1) ? bb : bc;
    float*       C    = (blockIdx.z == 0) ? Ca : (blockIdx.z == 1) ? Cb : Cc;

    __shared__ __align__(16) union SmemU {
        struct { float As[2][64][20]; float Bs[2][16][136]; } mm;
        float Ct[64][132];
    } su;

    const int bm = blockIdx.y * 64;
    const int tid = threadIdx.x, warp = tid >> 5, lane = tid & 31;
    const int wm = warp & 1, wn = warp >> 1;
    const int g = lane >> 2, t = lane & 3;

    const int ra = tid >> 2,  ca = (tid & 3) * 4;
    const int rb = tid >> 5,  cb = (tid & 31) * 4;

    float acc[2][4][4] = {};

    const int niter = K >> 4;
    cp_async16(&su.mm.As[0][ra][ca],   A + (size_t)(bm + ra) * K + ca);
    cp_async16(&su.mm.Bs[0][rb][cb],   W + (size_t)rb * N + cb);
    cp_async16(&su.mm.Bs[0][rb+8][cb], W + (size_t)(rb + 8) * N + cb);
    asm volatile("cp.async.commit_group;\n");

    for (int it = 0; it < niter; it++) {
        const int cur = it & 1;
        if (it + 1 < niter) {
            const int nxt = cur ^ 1, k0 = (it + 1) << 4;
            cp_async16(&su.mm.As[nxt][ra][ca],   A + (size_t)(bm + ra) * K + k0 + ca);
            cp_async16(&su.mm.Bs[nxt][rb][cb],   W + (size_t)(k0 + rb) * N + cb);
            cp_async16(&su.mm.Bs[nxt][rb+8][cb], W + (size_t)(k0 + rb + 8) * N + cb);
            asm volatile("cp.async.commit_group;\n");
            asm volatile("cp.async.wait_group 1;\n");
        } else {
            asm volatile("cp.async.wait_group 0;\n");
        }
        __syncthreads();

        #pragma unroll
        for (int kk = 0; kk < 16; kk += 8) {
            unsigned a[2][4], bfr[4][2];
            #pragma unroll
            for (int i = 0; i < 2; i++) {
                int row = wm*32 + i*16 + g;
                a[i][0] = f2tf(su.mm.As[cur][row    ][kk + t    ]);
                a[i][1] = f2tf(su.mm.As[cur][row + 8][kk + t    ]);
                a[i][2] = f2tf(su.mm.As[cur][row    ][kk + t + 4]);
                a[i][3] = f2tf(su.mm.As[cur][row + 8][kk + t + 4]);
            }
            #pragma unroll
            for (int j = 0; j < 4; j++) {
                int col = wn*32 + j*8 + g;
                bfr[j][0] = f2tf(su.mm.Bs[cur][kk + t    ][col]);
                bfr[j][1] = f2tf(su.mm.Bs[cur][kk + t + 4][col]);
            }
            #pragma unroll
            for (int i = 0; i < 2; i++)
                #pragma unroll
                for (int j = 0; j < 4; j++)
                    mma_tf32(acc[i][j], a[i], bfr[j]);
        }
        __syncthreads();
    }

    if (resid == nullptr) {
        #pragma unroll
        for (int i = 0; i < 2; i++) {
            #pragma unroll
            for (int half = 0; half < 2; half++) {
                int r = bm + wm*32 + i*16 + g + half*8;
                #pragma unroll
                for (int j = 0; j < 4; j++) {
                    int n0 = wn*32 + j*8 + 2*t;
                    float d0 = acc[i][j][half*2]     + bias[n0];
                    float d1 = acc[i][j][half*2 + 1] + bias[n0 + 1];
                    if (relu) { d0 = fmaxf(d0, 0.f); d1 = fmaxf(d1, 0.f); }
                    C[(size_t)r*N + n0]     = d0;
                    C[(size_t)r*N + n0 + 1] = d1;
                }
            }
        }
    } else {
        // fused: C = LayerNorm(resid + acc + bias)
        #pragma unroll
        for (int i = 0; i < 2; i++) {
            #pragma unroll
            for (int half = 0; half < 2; half++) {
                int rl = wm*32 + i*16 + g + half*8;
                int rg = bm + rl;
                #pragma unroll
                for (int j = 0; j < 4; j++) {
                    int n0 = wn*32 + j*8 + 2*t;
                    su.Ct[rl][n0]     = acc[i][j][half*2]     + bias[n0]
                                        + resid[(size_t)rg*N + n0];
                    su.Ct[rl][n0 + 1] = acc[i][j][half*2 + 1] + bias[n0 + 1]
                                        + resid[(size_t)rg*N + n0 + 1];
                }
            }
        }
        __syncthreads();
        #pragma unroll
        for (int rr = 0; rr < 8; rr++) {
            int rl = warp*8 + rr;
            float v0 = su.Ct[rl][lane];
            float v1 = su.Ct[rl][lane + 32];
            float v2 = su.Ct[rl][lane + 64];
            float v3 = su.Ct[rl][lane + 96];
            float s = v0 + v1 + v2 + v3;
            #pragma unroll
            for (int off = 16; off > 0; off >>= 1)
                s += __shfl_xor_sync(0xffffffffu, s, off);
            float mu = s * (1.f/128.f);
            float d0 = v0 - mu, d1 = v1 - mu, d2 = v2 - mu, d3 = v3 - mu;
            float s2 = d0*d0 + d1*d1 + d2*d2 + d3*d3;
            #pragma unroll
            for (int off = 16; off > 0; off >>= 1)
                s2 += __shfl_xor_sync(0xffffffffu, s2, off);
            float inv = rsqrtf(s2 * (1.f/128.f) + 1e-5f);
            size_t base = (size_t)(bm + rl) * N;
            C[base + lane]      = d0 * inv * lng[lane]      + lnb[lane];
            C[base + lane + 32] = d1 * inv * lng[lane + 32] + lnb[lane + 32];
            C[base + lane + 64] = d2 * inv * lng[lane + 64] + lnb[lane + 64];
            C[base + lane + 96] = d3 * inv * lng[lane + 96] + lnb[lane + 96];
        }
    }
}

// ---------------- Head GEMM (small M, fp32) --------------------------------
__global__ __launch_bounds__(128)
void head_gemm(const float* __restrict__ A, const float* __restrict__ W,
               const float* __restrict__ bias, float* __restrict__ C,
               int M, int N, int K, int relu)
{
    __shared__ __align__(16) float As[8][128];
    const int bn = blockIdx.x * 128, bm = blockIdx.y * 8;
    const int tid = threadIdx.x;
    const int n = bn + tid;
    float acc[8] = {};
    for (int k0 = 0; k0 < K; k0 += 128) {
        int kc = min(128, K - k0);
        #pragma unroll
        for (int i = 0; i < 8; i++)
            As[i][tid] = (tid < kc) ? A[(size_t)(bm + i)*K + k0 + tid] : 0.f;
        __syncthreads();
        if (n < N) {
            for (int k = 0; k < kc; k += 4) {
                float w0 = W[(size_t)(k0 + k    )*N + n];
                float w1 = W[(size_t)(k0 + k + 1)*N + n];
                float w2 = W[(size_t)(k0 + k + 2)*N + n];
                float w3 = W[(size_t)(k0 + k + 3)*N + n];
                #pragma unroll
                for (int i = 0; i < 8; i++) {
                    float4 a = *reinterpret_cast<const float4*>(&As[i][k]);
                    acc[i] += a.x*w0 + a.y*w1 + a.z*w2 + a.w*w3;
                }
            }
        }
        __syncthreads();
    }
    if (n < N) {
        #pragma unroll
        for (int i = 0; i < 8; i++) {
            float v = acc[i] + bias[n];
            if (relu) v = fmaxf(v, 0.f);
            C[(size_t)(bm + i)*N + n] = v;
        }
    }
}

// ---------------- Embedding: warp per bag, float4 (proven) -----------------
__global__ void embed_kernel(const int* __restrict__ cat_arr,
                             const int* __restrict__ amt_arr,
                             const int* __restrict__ dt_arr,
                             const float4* __restrict__ cat4,
                             const float4* __restrict__ amt4,
                             const float4* __restrict__ dt4,
                             float4* __restrict__ x4)
{
    int tid = threadIdx.x, w = tid >> 5, lane = tid & 31;
    int bag = blockIdx.x * 4 + w;
    __shared__ int sc[4][64];
    __shared__ int sa[4][64];
    sc[w][lane]      = cat_arr[(size_t)bag*JJ + lane];
    sc[w][lane + 32] = cat_arr[(size_t)bag*JJ + lane + 32];
    sa[w][lane]      = amt_arr[(size_t)bag*JJ + lane];
    sa[w][lane + 32] = amt_arr[(size_t)bag*JJ + lane + 32];
    __syncwarp();
    float4 acc = make_float4(0.f, 0.f, 0.f, 0.f);
    #pragma unroll 4
    for (int j = 0; j < JJ; j++) {
        int c = sc[w][j];
        if (c != CATN) {
            float4 u = __ldg(&cat4[(size_t)c*32 + lane]);
            float4 v = __ldg(&amt4[(size_t)sa[w][j]*32 + lane]);
            acc.x += u.x + v.x; acc.y += u.y + v.y;
            acc.z += u.z + v.z; acc.w += u.w + v.w;
        }
    }
    float4 d = __ldg(&dt4[(size_t)dt_arr[bag]*32 + lane]);
    acc.x += d.x; acc.y += d.y; acc.z += d.z; acc.w += d.w;
    int b = bag >> 7, l = bag & 127;
    x4[((size_t)b*SS + l + 1)*32 + lane] = acc;
}

__global__ void id_kernel(const int* __restrict__ id_arr,
                          const float* __restrict__ id_tab)
{
    int b = blockIdx.x, e = threadIdx.x;
    g_x[(size_t)b*SS*EE + e] = id_tab[(size_t)id_arr[b]*EE + e];
}

// ---------------- Fused tensor-core attention v5 ----------------
// Single-pass tf32; 12 warps; paired n-tiles (A-fragment reuse) x even/odd-k
// accumulators -> 4 independent MMA chains, 4 LDS per MMA.
__global__ __launch_bounds__(ATH)
void attn_mma(const float* __restrict__ q, const float* __restrict__ k,
              const float* __restrict__ v, float* __restrict__ o)
{
    extern __shared__ float smem[];
    float* sS  = smem;
    float* sKT = smem + SS_FLOATS;
    float* sU  = sKT + SKT_FLOATS;

    const int blk = blockIdx.x;
    const int chunk = blk % NCHUNK;
    const int bh = blk / NCHUNK;
    const int b = bh >> 1, h = bh & 1;
    const int row0 = chunk * MCH;

    const int tid = threadIdx.x, wid = tid >> 5, lane = tid & 31;
    const int g = lane >> 2, t = lane & 3;

    // ---- load Q rounded to tf32 ----
    {
        float* sQ = sU;
        for (int idx = tid; idx < MCH*16; idx += ATH) {
            int r = idx >> 4, dc = (idx & 15) * 4;
            int i = row0 + r;
            float4 tq = make_float4(0.f, 0.f, 0.f, 0.f);
            if (i < SS)
                tq = *reinterpret_cast<const float4*>(&q[((size_t)b*SS + i)*EE + h*HD + dc]);
            sQ[r*QP + dc    ] = rnd_tf(tq.x);
            sQ[r*QP + dc + 1] = rnd_tf(tq.y);
            sQ[r*QP + dc + 2] = rnd_tf(tq.z);
            sQ[r*QP + dc + 3] = rnd_tf(tq.w);
        }
    }
    // ---- load K^T rounded; zero-pad ----
    for (int idx = tid; idx < SS*16; idx += ATH) {
        int j = idx >> 4, dc = (idx & 15) * 4;
        float4 tk = *reinterpret_cast<const float4*>(&k[((size_t)b*SS + j)*EE + h*HD + dc]);
        sKT[(dc    )*KTP + j] = rnd_tf(tk.x);
        sKT[(dc + 1)*KTP + j] = rnd_tf(tk.y);
        sKT[(dc + 2)*KTP + j] = rnd_tf(tk.z);
        sKT[(dc + 3)*KTP + j] = rnd_tf(tk.w);
    }
    for (int idx = tid; idx < 64*(SPN - SS); idx += ATH) {
        int d = idx / (SPN - SS), j = SS + idx % (SPN - SS);
        sKT[d*KTP + j] = 0.f;
    }
    __syncthreads();

    // ---- Phase 1: scores = Q @ K^T; 3 tm x 9 tn-pairs ----
    {
        const float* sQ = sU;
        for (int item = wid; item < 3*9; item += AW) {
            int tm = item / 9, p = item % 9;
            int r0 = tm*16 + g;
            if (p < 8) {
                int tn0 = 2*p, tn1 = 2*p + 1;
                int col0 = tn0*8 + g, col1 = tn1*8 + g;
                float ac[2][2][4] = {};
                #pragma unroll
                for (int ks = 0; ks < 8; ks += 2) {
                    int kk0 = ks * 8, kk1 = kk0 + 8;
                    unsigned a0[4], a1[4], b00[2], b10[2], b01[2], b11[2];
                    a0[0] = __float_as_uint(sQ[(r0    )*QP + kk0 + t    ]);
                    a0[1] = __float_as_uint(sQ[(r0 + 8)*QP + kk0 + t    ]);
                    a0[2] = __float_as_uint(sQ[(r0    )*QP + kk0 + t + 4]);
                    a0[3] = __float_as_uint(sQ[(r0 + 8)*QP + kk0 + t + 4]);
                    a1[0] = __float_as_uint(sQ[(r0    )*QP + kk1 + t    ]);
                    a1[1] = __float_as_uint(sQ[(r0 + 8)*QP + kk1 + t    ]);
                    a1[2] = __float_as_uint(sQ[(r0    )*QP + kk1 + t + 4]);
                    a1[3] = __float_as_uint(sQ[(r0 + 8)*QP + kk1 + t + 4]);
                    b00[0] = __float_as_uint(sKT[(kk0 + t    )*KTP + col0]);
                    b00[1] = __float_as_uint(sKT[(kk0 + t + 4)*KTP + col0]);
                    b10[0] = __float_as_uint(sKT[(kk0 + t    )*KTP + col1]);
                    b10[1] = __float_as_uint(sKT[(kk0 + t + 4)*KTP + col1]);
                    b01[0] = __float_as_uint(sKT[(kk1 + t    )*KTP + col0]);
                    b01[1] = __float_as_uint(sKT[(kk1 + t + 4)*KTP + col0]);
                    b11[0] = __float_as_uint(sKT[(kk1 + t    )*KTP + col1]);
                    b11[1] = __float_as_uint(sKT[(kk1 + t + 4)*KTP + col1]);
                    mma_tf32(ac[0][0], a0, b00);
                    mma_tf32(ac[1][0], a0, b10);
                    mma_tf32(ac[0][1], a1, b01);
                    mma_tf32(ac[1][1], a1, b11);
                }
                #pragma unroll
                for (int n = 0; n < 2; n++) {
                    int c0 = (2*p + n)*8 + 2*t;
                    sS[(r0    )*SSP + c0    ] = (ac[n][0][0] + ac[n][1][0]) * 0.125f;
                    sS[(r0    )*SSP + c0 + 1] = (ac[n][0][1] + ac[n][1][1]) * 0.125f;
                    sS[(r0 + 8)*SSP + c0    ] = (ac[n][0][2] + ac[n][1][2]) * 0.125f;
                    sS[(r0 + 8)*SSP + c0 + 1] = (ac[n][0][3] + ac[n][1][3]) * 0.125f;
                }
            } else {   // lone tile tn = 16, dual-k chains
                int col = 16*8 + g;
                float ac0[4] = {}, ac1[4] = {};
                #pragma unroll
                for (int ks = 0; ks < 8; ks += 2) {
                    int kk0 = ks * 8, kk1 = kk0 + 8;
                    unsigned a0[4], a1[4], b0[2], b1[2];
                    a0[0] = __float_as_uint(sQ[(r0    )*QP + kk0 + t    ]);
                    a0[1] = __float_as_uint(sQ[(r0 + 8)*QP + kk0 + t    ]);
                    a0[2] = __float_as_uint(sQ[(r0    )*QP + kk0 + t + 4]);
                    a0[3] = __float_as_uint(sQ[(r0 + 8)*QP + kk0 + t + 4]);
                    a1[0] = __float_as_uint(sQ[(r0    )*QP + kk1 + t    ]);
                    a1[1] = __float_as_uint(sQ[(r0 + 8)*QP + kk1 + t    ]);
                    a1[2] = __float_as_uint(sQ[(r0    )*QP + kk1 + t + 4]);
                    a1[3] = __float_as_uint(sQ[(r0 + 8)*QP + kk1 + t + 4]);
                    b0[0] = __float_as_uint(sKT[(kk0 + t    )*KTP + col]);
                    b0[1] = __float_as_uint(sKT[(kk0 + t + 4)*KTP + col]);
                    b1[0] = __float_as_uint(sKT[(kk1 + t    )*KTP + col]);
                    b1[1] = __float_as_uint(sKT[(kk1 + t + 4)*KTP + col]);
                    mma_tf32(ac0, a0, b0);
                    mma_tf32(ac1, a1, b1);
                }
                int c0 = 16*8 + 2*t;
                sS[(r0    )*SSP + c0    ] = (ac0[0] + ac1[0]) * 0.125f;
                sS[(r0    )*SSP + c0 + 1] = (ac0[1] + ac1[1]) * 0.125f;
                sS[(r0 + 8)*SSP + c0    ] = (ac0[2] + ac1[2]) * 0.125f;
                sS[(r0 + 8)*SSP + c0 + 1] = (ac0[3] + ac1[3]) * 0.125f;
            }
        }
    }
    __syncthreads();

    // ---- Phase 2: softmax; write P rounded to tf32 ----
    for (int r = wid; r < MCH; r += AW) {
        int i = row0 + r;
        if (i < SS) {
            float pr[5];
            float mx = -1e30f;
            #pragma unroll
            for (int m = 0; m < 5; m++) {
                int j = lane + m*32;
                float s = (j < SS) ? sS[r*SSP + j] : -1e30f;
                pr[m] = s;
                mx = fmaxf(mx, s);
            }
            #pragma unroll
            for (int off = 16; off > 0; off >>= 1)
                mx = fmaxf(mx, __shfl_xor_sync(0xffffffffu, mx, off));
            float sum = 0.f;
            #pragma unroll
            for (int m = 0; m < 5; m++) {
                int j = lane + m*32;
                float e = (j < SS) ? __expf(pr[m] - mx) : 0.f;
                pr[m] = e; sum += e;
            }
            #pragma unroll
            for (int off = 16; off > 0; off >>= 1)
                sum += __shfl_xor_sync(0xffffffffu, sum, off);
            float inv = 1.f / sum;
            #pragma unroll
            for (int m = 0; m < 5; m++) {
                int j = lane + m*32;
                if (j < SPN)
                    sS[r*SSP + j] = (j < SS) ? rnd_tf(pr[m] * inv) : 0.f;
            }
        } else {
            #pragma unroll
            for (int m = 0; m < 5; m++) {
                int j = lane + m*32;
                if (j < SPN) sS[r*SSP + j] = 0.f;
            }
        }
    }
    // ---- load V rounded into union ----
    {
        float* sV = sU;
        for (int idx = tid; idx < SPN*16; idx += ATH) {
            int j = idx >> 4, dc = (idx & 15) * 4;
            float4 tv = make_float4(0.f, 0.f, 0.f, 0.f);
            if (j < SS)
                tv = *reinterpret_cast<const float4*>(&v[((size_t)b*SS + j)*EE + h*HD + dc]);
            sV[j*VP + dc    ] = rnd_tf(tv.x);
            sV[j*VP + dc + 1] = rnd_tf(tv.y);
            sV[j*VP + dc + 2] = rnd_tf(tv.z);
            sV[j*VP + dc + 3] = rnd_tf(tv.w);
        }
    }
    __syncthreads();

    // ---- Phase 3: out = P @ V; 3 tm x 4 tn-pairs = 12 items (1/warp) ------
    {
        const float* sV = sU;
        int item = wid;                   // 12 warps, 12 items
        int tm = item >> 2, pp = item & 3;
        int tn0 = 2*pp, tn1 = 2*pp + 1;
        int r0 = tm*16 + g;
        int col0 = tn0*8 + g, col1 = tn1*8 + g;
        float ac[2][2][4] = {};
        #pragma unroll
        for (int ks = 0; ks < 16; ks += 2) {
            int kk0 = ks * 8, kk1 = kk0 + 8;
            unsigned a0[4], a1[4], b00[2], b10[2], b01[2], b11[2];
            a0[0] = __float_as_uint(sS[(r0    )*SSP + kk0 + t    ]);
            a0[1] = __float_as_uint(sS[(r0 + 8)*SSP + kk0 + t    ]);
            a0[2] = __float_as_uint(sS[(r0    )*SSP + kk0 + t + 4]);
            a0[3] = __float_as_uint(sS[(r0 + 8)*SSP + kk0 + t + 4]);
            a1[0] = __float_as_uint(sS[(r0    )*SSP + kk1 + t    ]);
            a1[1] = __float_as_uint(sS[(r0 + 8)*SSP + kk1 + t    ]);
            a1[2] = __float_as_uint(sS[(r0    )*SSP + kk1 + t + 4]);
            a1[3] = __float_as_uint(sS[(r0 + 8)*SSP + kk1 + t + 4]);
            b00[0] = __float_as_uint(sV[(kk0 + t    )*VP + col0]);
            b00[1] = __float_as_uint(sV[(kk0 + t + 4)*VP + col0]);
            b10[0] = __float_as_uint(sV[(kk0 + t    )*VP + col1]);
            b10[1] = __float_as_uint(sV[(kk0 + t + 4)*VP + col1]);
            b01[0] = __float_as_uint(sV[(kk1 + t    )*VP + col0]);
            b01[1] = __float_as_uint(sV[(kk1 + t + 4)*VP + col0]);
            b11[0] = __float_as_uint(sV[(kk1 + t    )*VP + col1]);
            b11[1] = __float_as_uint(sV[(kk1 + t + 4)*VP + col1]);
            mma_tf32(ac[0][0], a0, b00);
            mma_tf32(ac[1][0], a0, b10);
            mma_tf32(ac[0][1], a1, b01);
            mma_tf32(ac[1][1], a1, b11);
        }
        {   // tail k-step ks = 16
            int kk = 16 * 8;
            unsigned a[4], b0[2], b1[2];
            a[0] = __float_as_uint(sS[(r0    )*SSP + kk + t    ]);
            a[1] = __float_as_uint(sS[(r0 + 8)*SSP + kk + t    ]);
            a[2] = __float_as_uint(sS[(r0    )*SSP + kk + t + 4]);
            a[3] = __float_as_uint(sS[(r0 + 8)*SSP + kk + t + 4]);
            b0[0] = __float_as_uint(sV[(kk + t    )*VP + col0]);
            b0[1] = __float_as_uint(sV[(kk + t + 4)*VP + col0]);
            b1[0] = __float_as_uint(sV[(kk + t    )*VP + col1]);
            b1[1] = __float_as_uint(sV[(kk + t + 4)*VP + col1]);
            mma_tf32(ac[0][0], a, b0);
            mma_tf32(ac[1][0], a, b1);
        }
        int i0 = row0 + tm*16 + g;
        #pragma unroll
        for (int n = 0; n < 2; n++) {
            int c0 = (2*pp + n)*8 + 2*t;
            if (i0 < SS) {
                float* orow = &o[((size_t)b*SS + i0)*EE + h*HD];
                orow[c0]     = ac[n][0][0] + ac[n][1][0];
                orow[c0 + 1] = ac[n][0][1] + ac[n][1][1];
            }
            if (i0 + 8 < SS) {
                float* orow = &o[((size_t)b*SS + i0 + 8)*EE + h*HD];
                orow[c0]     = ac[n][0][2] + ac[n][1][2];
                orow[c0 + 1] = ac[n][0][3] + ac[n][1][3];
            }
        }
    }
}

// ---------------- Mean pool ----------------
__global__ void pool_kernel(const float* __restrict__ x, float* __restrict__ h)
{
    int b = blockIdx.x, e = threadIdx.x;
    float s = 0.f;
    #pragma unroll 4
    for (int l = 1; l <= LL; l++) s += x[((size_t)b*SS + l)*EE + e];
    h[(size_t)b*EE + e] = s * (1.f/128.f);
}

// ---------------- Launch ----------------
extern "C" void kernel_launch(void* const* d_in, const int* in_sizes, int n_in,
                              void* d_out, int out_size)
{
    (void)in_sizes; (void)n_in; (void)out_size;
    const int*   cat_arr = (const int*)  d_in[0];
    const int*   dt_arr  = (const int*)  d_in[1];
    const int*   amt_arr = (const int*)  d_in[2];
    const int*   id_arr  = (const int*)  d_in[3];
    const float* id_tab  = (const float*)d_in[4];
    const float* cat_tab = (const float*)d_in[5];
    const float* amt_tab = (const float*)d_in[6];
    const float* dt_tab  = (const float*)d_in[7];
    const float* Wq = (const float*)d_in[8],  *bq = (const float*)d_in[9];
    const float* Wk = (const float*)d_in[10], *bk = (const float*)d_in[11];
    const float* Wv = (const float*)d_in[12], *bv = (const float*)d_in[13];
    const float* Wo = (const float*)d_in[14], *bo = (const float*)d_in[15];
    const float* ln1g = (const float*)d_in[16], *ln1b = (const float*)d_in[17];
    const float* W1 = (const float*)d_in[18], *b1 = (const float*)d_in[19];
    const float* W2 = (const float*)d_in[20], *b2 = (const float*)d_in[21];
    const float* ln2g = (const float*)d_in[22], *ln2b = (const float*)d_in[23];
    const float* l1W = (const float*)d_in[24], *l1b = (const float*)d_in[25];
    const float* l2W = (const float*)d_in[26], *l2b = (const float*)d_in[27];
    float* out = (float*)d_out;

    float *x, *q, *k, *v, *o, *f1, *h, *x1;
    cudaGetSymbolAddress((void**)&x,   g_x);
    cudaGetSymbolAddress((void**)&q,   g_q);
    cudaGetSymbolAddress((void**)&k,   g_k);
    cudaGetSymbolAddress((void**)&v,   g_v);
    cudaGetSymbolAddress((void**)&o,   g_o);
    cudaGetSymbolAddress((void**)&f1,  g_f1);
    cudaGetSymbolAddress((void**)&h,   g_h);
    cudaGetSymbolAddress((void**)&x1,  g_x1);

    static int attn_smem_set = 0;
    if (!attn_smem_set) {
        cudaFuncSetAttribute(attn_mma,
                             cudaFuncAttributeMaxDynamicSharedMemorySize,
                             ATTN_SMEM_BYTES);
        attn_smem_set = 1;
    }

    // 1. embeddings
    embed_kernel<<<BB*LL/4, 128>>>(cat_arr, amt_arr, dt_arr,
                                   (const float4*)cat_tab, (const float4*)amt_tab,
                                   (const float4*)dt_tab, (float4*)x);
    id_kernel<<<BB, EE>>>(id_arr, id_tab);

    // 2. QKV: one batched launch (z = 0,1,2)
    dim3 gQKV(1, ROWS/64, 3);
    gemm_tf32<<<gQKV, 256>>>(x, Wq, Wk, Wv, bq, bk, bv, q, k, v, EE, EE, 0,
                             nullptr, nullptr, nullptr);

    // 3. fused tensor-core attention
    attn_mma<<<BB*HH*NCHUNK, ATH, ATTN_SMEM_BYTES>>>(q, k, v, o);

    // 4. out proj + fused residual + LN1:  x = LN(x + o@Wo + bo)
    dim3 g1(1, ROWS/64, 1);
    gemm_tf32<<<g1, 256>>>(o, Wo, Wo, Wo, bo, bo, bo, x, x, x, EE, EE, 0,
                           x, ln1g, ln1b);

    // 5. FFN:  f1 = relu(x@W1 + b1);  x = LN(x + f1@W2 + b2)
    gemm_tf32<<<g1, 256>>>(x,  W1, W1, W1, b1, b1, b1, f1, f1, f1, EE, EE, 1,
                           nullptr, nullptr, nullptr);
    gemm_tf32<<<g1, 256>>>(f1, W2, W2, W2, b2, b2, b2, x, x, x, EE, EE, 0,
                           x, ln2g, ln2b);

    // 6. pool + classifier head
    pool_kernel<<<BB, EE>>>(x, h);
    dim3 gH1((CATN + 127)/128, BB/8);
    head_gemm<<<gH1, 128>>>(h,  l1W, l1b, x1,  BB, CATN, EE,   1);
    head_gemm<<<gH1, 128>>>(x1, l2W, l2b, out, BB, CATN, CATN, 0);
}